// round 3
// baseline (speedup 1.0000x reference)
#include <cuda_runtime.h>

// Problem constants
#define DSZ 192            // each spatial dim
#define NB  2              // batch
#define TX  32             // tile width  (x, contiguous dim)
#define TY  16             // tile height (y)
#define ZCH 48             // z outputs per block
#define NZB (DSZ / ZCH)    // 4 z-chunks
#define NT  512            // threads per block

#define KRAD 2             // kernel radius (5x5x5)
#define HROWS (TY + 4)     // xsum rows incl. y halo = 20

static __device__ __forceinline__ float4 f4add(float4 a, float4 b) {
    return make_float4(a.x + b.x, a.y + b.y, a.z + b.z, a.w + b.w);
}

__global__ void hx_zero_out(float* out) { out[0] = 0.0f; }

__global__ __launch_bounds__(NT, 2)
void lncc_kernel(const float* __restrict__ pred,
                 const float* __restrict__ targ,
                 float* __restrict__ out)
{
    // x-filtered sums of the 5 channels: (I, J, I2, J2) packed in float4, IJ separate
    __shared__ float4 xsA[HROWS * TX];
    __shared__ float  xsB[HROWS * TX];
    // (x,y)-filtered sums
    __shared__ float4 sdA[TY * TX];
    __shared__ float  sdB[TY * TX];
    __shared__ float  blockAcc;

    const int tid   = threadIdx.x;
    const int bx    = blockIdx.x;              // 6 tiles in x
    const int by    = blockIdx.y;              // 12 tiles in y
    const int batch = blockIdx.z / NZB;        // 2 batches
    const int z0    = (blockIdx.z % NZB) * ZCH;

    if (tid == 0) blockAcc = 0.0f;

    // ---- Stage B constants: 160 active threads, each = (row, 4-wide x chunk) ----
    const int  rowB  = tid >> 3;               // 0..63 (active < HROWS)
    const int  xcB   = tid & 7;                // 8 chunks of 4 -> 32 x outputs
    const bool bAct  = (tid < HROWS * 8);
    const int  gy    = by * TY + rowB - KRAD;  // global y for this xsum row
    const bool gyok  = bAct && (gy >= 0) && (gy < DSZ);
    const int  gx0   = bx * TX + xcB * 4 - KRAD;  // leftmost of 8 consecutive x reads
    const int  rowOff = gy * DSZ;              // row offset within a z-plane (may be garbage if !gyok)

    // ---- Stage C constants: 128 active threads, each = (4-wide y chunk, x) ----
    const int  cyC  = tid >> 5;                // 0..15 (active < 4)
    const int  cxC  = tid & 31;
    const bool cAct = (tid < 4 * TX);

    // ---- Stage D constants: all 512 threads, each owns one (y,x) output column ----
    const int dy = tid >> 5;                   // 0..15
    const int dx = tid & 31;

    // z ring: last 5 (x,y)-filtered planes for this thread's column (registers)
    float4 r0 = make_float4(0.f,0.f,0.f,0.f), r1 = r0, r2 = r0, r3 = r0, r4 = r0;
    float  b0 = 0.f, b1 = 0.f, b2 = 0.f, b3 = 0.f, b4 = 0.f;

    const int planeStride = DSZ * DSZ;
    const int batchOff    = batch * DSZ * planeStride;

    float acc = 0.0f;

    const float INV125 = 1.0f / 125.0f;
    const float SMOOTH = 1e-5f;

    for (int zi = z0 - KRAD; zi < z0 + ZCH + KRAD; ++zi) {
        const bool zv = (zi >= 0) && (zi < DSZ);

        // ================= Stage B: global load + x-direction window sums =================
        if (zv && bAct) {
            float pv[8], tv[8];
            const int base = batchOff + zi * planeStride + rowOff;
            #pragma unroll
            for (int k = 0; k < 8; ++k) {
                const int gx = gx0 + k;
                const bool ok = gyok && (gx >= 0) && (gx < DSZ);
                pv[k] = ok ? __ldg(pred + base + gx) : 0.0f;
                tv[k] = ok ? __ldg(targ + base + gx) : 0.0f;
            }
            #pragma unroll
            for (int o = 0; o < 4; ++o) {
                float4 s = make_float4(0.f, 0.f, 0.f, 0.f);
                float  sij = 0.f;
                #pragma unroll
                for (int k = o; k < o + 5; ++k) {
                    const float p = pv[k], t = tv[k];
                    s.x += p;     s.y += t;
                    s.z += p * p; s.w += t * t;
                    sij += p * t;
                }
                const int idx = rowB * TX + xcB * 4 + o;
                xsA[idx] = s;
                xsB[idx] = sij;
            }
        }
        __syncthreads();

        // ================= Stage C: y-direction window sums (coarsened x4) =================
        if (zv && cAct) {
            float4 a0 = make_float4(0.f,0.f,0.f,0.f), a1 = a0, a2 = a0, a3 = a0;
            float  e0 = 0.f, e1 = 0.f, e2 = 0.f, e3 = 0.f;
            #pragma unroll
            for (int r = 0; r < 8; ++r) {
                const float4 v  = xsA[(cyC * 4 + r) * TX + cxC];
                const float  vb = xsB[(cyC * 4 + r) * TX + cxC];
                // output j consumes rows r in [j, j+4]
                if (r <= 4)           { a0 = f4add(a0, v); e0 += vb; }
                if (r >= 1 && r <= 5) { a1 = f4add(a1, v); e1 += vb; }
                if (r >= 2 && r <= 6) { a2 = f4add(a2, v); e2 += vb; }
                if (r >= 3)           { a3 = f4add(a3, v); e3 += vb; }
            }
            const int o = (cyC * 4) * TX + cxC;
            sdA[o + 0 * TX] = a0;  sdB[o + 0 * TX] = e0;
            sdA[o + 1 * TX] = a1;  sdB[o + 1 * TX] = e1;
            sdA[o + 2 * TX] = a2;  sdB[o + 2 * TX] = e2;
            sdA[o + 3 * TX] = a3;  sdB[o + 3 * TX] = e3;
        }
        __syncthreads();

        // ================= Stage D: z ring + NCC =================
        float4 nv;
        float  nb;
        if (zv) {
            nv = sdA[dy * TX + dx];
            nb = sdB[dy * TX + dx];
        } else {
            nv = make_float4(0.f, 0.f, 0.f, 0.f);
            nb = 0.f;
        }
        // shift ring, append newest
        r0 = r1; r1 = r2; r2 = r3; r3 = r4; r4 = nv;
        b0 = b1; b1 = b2; b2 = b3; b3 = b4; b4 = nb;

        const int oz = zi - KRAD;
        if (oz >= z0) {
            // full 5-plane z sums
            float4 S = f4add(f4add(f4add(r0, r1), f4add(r2, r3)), r4);
            float  Sb = b0 + b1 + b2 + b3 + b4;

            const float uI = S.x * INV125;
            const float uJ = S.y * INV125;
            const float cross = Sb  * INV125 - uI * uJ;
            const float var_i = S.z * INV125 - uI * uI;
            const float var_j = S.w * INV125 - uJ * uJ;
            const float ncc = (cross * cross) / (var_i * var_j + SMOOTH);
            acc += ncc;
        }
        // No sync needed here: the sync after next stage B separates this D read
        // from the next C write of sdA/sdB.
    }

    // ================= Reduction =================
    #pragma unroll
    for (int off = 16; off > 0; off >>= 1)
        acc += __shfl_xor_sync(0xffffffffu, acc, off);
    if ((tid & 31) == 0)
        atomicAdd(&blockAcc, acc);
    __syncthreads();
    if (tid == 0) {
        const float INVN = 1.0f / (float)(NB * DSZ * DSZ * DSZ);
        atomicAdd(out, -blockAcc * INVN);
    }
}

extern "C" void kernel_launch(void* const* d_in, const int* in_sizes, int n_in,
                              void* d_out, int out_size)
{
    const float* pred = (const float*)d_in[0];
    const float* targ = (const float*)d_in[1];
    float* out = (float*)d_out;

    hx_zero_out<<<1, 1>>>(out);

    dim3 grid(DSZ / TX, DSZ / TY, NB * NZB);   // 6 x 12 x 8 = 576 blocks
    lncc_kernel<<<grid, NT>>>(pred, targ, out);
}

// round 4
// speedup vs baseline: 1.3650x; 1.3650x over previous
#include <cuda_runtime.h>

#define DSZ 192
#define PL  (DSZ * DSZ)          // 36864 floats per z-plane
#define NB  2
#define TX  64                   // tile width (x)
#define TY  4                    // tile height (y)
#define ZCH 96                   // z outputs per block (2 chunks cover 192)
#define NT  256                  // threads per block
#define HR  8                    // xs rows incl. y halo = TY + 4
#define ITERS (ZCH + 4)          // 100 planes per block (divisible by 5)

__global__ void hx_zero_out(float* out) { out[0] = 0.0f; }

__global__ __launch_bounds__(NT, 4)
void lncc_kernel(const float* __restrict__ pred,
                 const float* __restrict__ targ,
                 float* __restrict__ out)
{
    // x-filtered window sums, double buffered.
    // Packed so stores/loads are wide and conflict-free:
    //   sAB = (sumI, sumJ), sCD = (sumI2, sumJ2), sE = sumIJ
    __shared__ float2 sAB[2][HR][TX];
    __shared__ float2 sCD[2][HR][TX];
    __shared__ float  sE [2][HR][TX];
    __shared__ float  blockAcc;

    const int tid = threadIdx.x;
    const int bx = blockIdx.x, by = blockIdx.y;
    const int batch = blockIdx.z >> 1;           // 2 z-chunks per batch
    const int z0    = (blockIdx.z & 1) * ZCH;

    if (tid == 0) blockAcc = 0.0f;

    // ---- Stage B mapping: warp = one xs row, lane = pair of x outputs ----
    const int  r   = tid >> 5;                   // 0..7
    const int  px  = tid & 31;
    const int  sx  = 2 * px;                     // first of 2 x outputs
    const int  gy  = by * TY + r - 2;
    const int  gx0 = bx * TX + sx - 2;           // leftmost of 6 input floats (even!)
    const bool rowok = (unsigned)gy < (unsigned)DSZ;
    const bool c0 = rowok && ((unsigned)(gx0    ) < (unsigned)DSZ);
    const bool c1 = rowok && ((unsigned)(gx0 + 2) < (unsigned)DSZ);
    const bool c2 = rowok && ((unsigned)(gx0 + 4) < (unsigned)DSZ);

    const int gyc = gy < 0 ? 0 : (gy > DSZ - 1 ? DSZ - 1 : gy);
    const long off = (long)batch * DSZ * PL + (long)gyc * DSZ + gx0;
    const float* pB = pred + off;
    const float* tB = targ + off;

    // ---- Stage D mapping: one (y,x) output column per thread ----
    const int dy = tid >> 6;                     // 0..3
    const int dx = tid & 63;

    float2 pa0, pa1, pa2, ta0, ta1, ta2;         // prefetch registers
    const float2 Z2 = make_float2(0.f, 0.f);

#define PREF(ZI) do {                                                   \
        const int  zi_  = (ZI);                                         \
        const bool zok_ = (unsigned)zi_ < (unsigned)DSZ;                \
        const long po_  = (long)(zok_ ? zi_ : 0) * PL;                  \
        pa0 = (zok_ && c0) ? *(const float2*)(pB + po_    ) : Z2;       \
        pa1 = (zok_ && c1) ? *(const float2*)(pB + po_ + 2) : Z2;       \
        pa2 = (zok_ && c2) ? *(const float2*)(pB + po_ + 4) : Z2;       \
        ta0 = (zok_ && c0) ? *(const float2*)(tB + po_    ) : Z2;       \
        ta1 = (zok_ && c1) ? *(const float2*)(tB + po_ + 2) : Z2;       \
        ta2 = (zok_ && c2) ? *(const float2*)(tB + po_ + 4) : Z2;       \
    } while (0)

#define BSTAGE(BUF) do {                                                        \
        const float p0=pa0.x, p1=pa0.y, p2=pa1.x, p3=pa1.y, p4=pa2.x, p5=pa2.y; \
        const float q0=ta0.x, q1=ta0.y, q2=ta1.x, q3=ta1.y, q4=ta2.x, q5=ta2.y; \
        const float aI  = p0 + p1 + p2 + p3 + p4;                               \
        const float aJ  = q0 + q1 + q2 + q3 + q4;                               \
        const float aII = fmaf(p4,p4, fmaf(p3,p3, fmaf(p2,p2, fmaf(p1,p1, p0*p0)))); \
        const float aJJ = fmaf(q4,q4, fmaf(q3,q3, fmaf(q2,q2, fmaf(q1,q1, q0*q0)))); \
        const float aIJ = fmaf(p4,q4, fmaf(p3,q3, fmaf(p2,q2, fmaf(p1,q1, p0*q0)))); \
        const float bI  = aI - p0 + p5;                                         \
        const float bJ  = aJ - q0 + q5;                                         \
        const float bII = fmaf(p5,p5, fmaf(-p0,p0, aII));                       \
        const float bJJ = fmaf(q5,q5, fmaf(-q0,q0, aJJ));                       \
        const float bIJ = fmaf(p5,q5, fmaf(-p0,q0, aIJ));                       \
        *(float4*)&sAB[BUF][r][sx] = make_float4(aI,  aJ,  bI,  bJ );           \
        *(float4*)&sCD[BUF][r][sx] = make_float4(aII, aJJ, bII, bJJ);           \
        *(float2*)&sE [BUF][r][sx] = make_float2(aIJ, bIJ);                     \
    } while (0)

    // z ring (5 slots, statically indexed inside the x5-unrolled loop) and
    // incremental 5-plane z sums.
    float rgI[5], rgJ[5], rgII[5], rgJJ[5], rgIJ[5];
#pragma unroll
    for (int s = 0; s < 5; ++s) { rgI[s]=0.f; rgJ[s]=0.f; rgII[s]=0.f; rgJJ[s]=0.f; rgIJ[s]=0.f; }
    float SzI=0.f, SzJ=0.f, SzII=0.f, SzJJ=0.f, SzIJ=0.f;
    float acc = 0.f;

    PREF(z0 - 2);   // plane for it = 0

    for (int base = 0; base < ITERS; base += 5) {
#pragma unroll
        for (int s = 0; s < 5; ++s) {
            const int it  = base + s;
            const int buf = it & 1;

            // B: x-window sums of plane (z0-2+it) from prefetched regs
            BSTAGE(buf);
            // prefetch next plane (overlaps the barrier + D stage)
            if (it < ITERS - 1) PREF(z0 - 1 + it);
            __syncthreads();

            // D: y-window sum for this thread's column
            float yI=0.f, yJ=0.f, yII=0.f, yJJ=0.f, yIJ=0.f;
#pragma unroll
            for (int j = 0; j < 5; ++j) {
                const float2 ab = sAB[buf][dy + j][dx];
                const float2 cd = sCD[buf][dy + j][dx];
                const float  e  = sE [buf][dy + j][dx];
                yI += ab.x; yJ += ab.y; yII += cd.x; yJJ += cd.y; yIJ += e;
            }

            // incremental z-window sum: add newest, subtract 5-planes-old
            SzI  += yI  - rgI [s];  rgI [s] = yI;
            SzJ  += yJ  - rgJ [s];  rgJ [s] = yJ;
            SzII += yII - rgII[s];  rgII[s] = yII;
            SzJJ += yJJ - rgJJ[s];  rgJJ[s] = yJJ;
            SzIJ += yIJ - rgIJ[s];  rgIJ[s] = yIJ;

            if (it >= 4) {   // first complete window at output plane z0
                const float INV = 1.0f / 125.0f;
                const float uI = SzI * INV, uJ = SzJ * INV;
                const float cross = fmaf(-uI, uJ, SzIJ * INV);
                const float vi    = fmaf(-uI, uI, SzII * INV);
                const float vj    = fmaf(-uJ, uJ, SzJJ * INV);
                acc += __fdividef(cross * cross, fmaf(vi, vj, 1e-5f));
            }
        }
    }

#undef PREF
#undef BSTAGE

    // ---- Reduction ----
#pragma unroll
    for (int o = 16; o > 0; o >>= 1)
        acc += __shfl_xor_sync(0xffffffffu, acc, o);
    if ((tid & 31) == 0)
        atomicAdd(&blockAcc, acc);
    __syncthreads();
    if (tid == 0) {
        const float INVN = 1.0f / (float)((long)NB * DSZ * DSZ * DSZ);
        atomicAdd(out, -blockAcc * INVN);
    }
}

extern "C" void kernel_launch(void* const* d_in, const int* in_sizes, int n_in,
                              void* d_out, int out_size)
{
    const float* pred = (const float*)d_in[0];
    const float* targ = (const float*)d_in[1];
    float* out = (float*)d_out;

    hx_zero_out<<<1, 1>>>(out);

    dim3 grid(DSZ / TX, DSZ / TY, NB * (DSZ / ZCH));   // 3 x 48 x 4 = 576 blocks
    lncc_kernel<<<grid, NT>>>(pred, targ, out);
}

// round 5
// speedup vs baseline: 1.8856x; 1.3814x over previous
#include <cuda_runtime.h>

#define DSZ 192
#define PL  (DSZ * DSZ)          // floats per z-plane
#define NB  2
#define TX  64                   // tile width (x)
#define TY  8                    // tile height (y outputs per plane)
#define ZCH 96                   // z outputs per block
#define NT  256                  // threads per block
#define HR  12                   // x-sum rows incl. y halo = TY + 4
#define ITERS (ZCH + 4)          // 100 planes per block

__global__ void hx_zero_out(float* out) { out[0] = 0.0f; }

__global__ __launch_bounds__(NT, 2)
void lncc_kernel(const float* __restrict__ pred,
                 const float* __restrict__ targ,
                 float* __restrict__ out)
{
    // x-filtered window sums, channel-major, double buffered.
    // channels: 0=I, 1=J, 2=I2, 3=J2, 4=IJ
    __shared__ float sh[2][5][HR][TX];
    __shared__ float blockAcc;

    const int tid = threadIdx.x;
    const int bx = blockIdx.x, by = blockIdx.y;
    const int batch = blockIdx.z >> 1;
    const int z0    = (blockIdx.z & 1) * ZCH;

    if (tid == 0) blockAcc = 0.0f;

    // ---- Stage B mapping: 192 active threads = 12 rows x 16 x-chunks of 4 ----
    const int  r    = tid >> 4;                 // 0..15 (active < 12)
    const int  xq   = tid & 15;
    const bool bAct = (r < HR);
    const int  gy   = by * TY + r - 2;
    const bool rowok = bAct && ((unsigned)gy < (unsigned)DSZ);
    const int  gx0  = bx * TX + 4 * xq - 2;     // leftmost of 8 input floats (even)
    const bool c0 = rowok && ((unsigned)(gx0    ) <= 190u);
    const bool c1 = rowok && ((unsigned)(gx0 + 2) <= 190u);
    const bool c2 = rowok && ((unsigned)(gx0 + 4) <= 190u);
    const bool c3 = rowok && ((unsigned)(gx0 + 6) <= 190u);

    const int gyc = gy < 0 ? 0 : (gy > DSZ - 1 ? DSZ - 1 : gy);
    const long off = (long)batch * DSZ * PL + (long)gyc * DSZ + gx0;
    const float* pB = pred + off;
    const float* tB = targ + off;

    // ---- Stage D mapping: each thread owns 2 adjacent y outputs ----
    const int dy = (tid >> 6) * 2;              // 0,2,4,6
    const int dx = tid & 63;

    float2 pa0, pa1, pa2, pa3, ta0, ta1, ta2, ta3;   // prefetch regs
    const float2 Z2 = make_float2(0.f, 0.f);

#define PREF(ZI) do {                                                     \
        const int  zi_  = (ZI);                                           \
        const bool zok_ = (unsigned)zi_ < (unsigned)DSZ;                  \
        const long po_  = (long)(zok_ ? zi_ : 0) * PL;                    \
        pa0 = (zok_ && c0) ? *(const float2*)(pB + po_    ) : Z2;         \
        pa1 = (zok_ && c1) ? *(const float2*)(pB + po_ + 2) : Z2;         \
        pa2 = (zok_ && c2) ? *(const float2*)(pB + po_ + 4) : Z2;         \
        pa3 = (zok_ && c3) ? *(const float2*)(pB + po_ + 6) : Z2;         \
        ta0 = (zok_ && c0) ? *(const float2*)(tB + po_    ) : Z2;         \
        ta1 = (zok_ && c1) ? *(const float2*)(tB + po_ + 2) : Z2;         \
        ta2 = (zok_ && c2) ? *(const float2*)(tB + po_ + 4) : Z2;         \
        ta3 = (zok_ && c3) ? *(const float2*)(tB + po_ + 6) : Z2;         \
    } while (0)

#define BSTAGE(BUF) do {                                                          \
        const float p0=pa0.x,p1=pa0.y,p2=pa1.x,p3=pa1.y,p4=pa2.x,p5=pa2.y,p6=pa3.x,p7=pa3.y; \
        const float q0=ta0.x,q1=ta0.y,q2=ta1.x,q3=ta1.y,q4=ta2.x,q5=ta2.y,q6=ta3.x,q7=ta3.y; \
        float4 oI, oJ, oII, oJJ, oIJ;                                             \
        oI.x = p0 + p1 + p2 + p3 + p4;                                            \
        oI.y = oI.x - p0 + p5;  oI.z = oI.y - p1 + p6;  oI.w = oI.z - p2 + p7;    \
        oJ.x = q0 + q1 + q2 + q3 + q4;                                            \
        oJ.y = oJ.x - q0 + q5;  oJ.z = oJ.y - q1 + q6;  oJ.w = oJ.z - q2 + q7;    \
        oII.x = fmaf(p4,p4, fmaf(p3,p3, fmaf(p2,p2, fmaf(p1,p1, p0*p0))));        \
        oII.y = fmaf(p5,p5, fmaf(-p0,p0, oII.x));                                 \
        oII.z = fmaf(p6,p6, fmaf(-p1,p1, oII.y));                                 \
        oII.w = fmaf(p7,p7, fmaf(-p2,p2, oII.z));                                 \
        oJJ.x = fmaf(q4,q4, fmaf(q3,q3, fmaf(q2,q2, fmaf(q1,q1, q0*q0))));        \
        oJJ.y = fmaf(q5,q5, fmaf(-q0,q0, oJJ.x));                                 \
        oJJ.z = fmaf(q6,q6, fmaf(-q1,q1, oJJ.y));                                 \
        oJJ.w = fmaf(q7,q7, fmaf(-q2,q2, oJJ.z));                                 \
        oIJ.x = fmaf(p4,q4, fmaf(p3,q3, fmaf(p2,q2, fmaf(p1,q1, p0*q0))));        \
        oIJ.y = fmaf(p5,q5, fmaf(-p0,q0, oIJ.x));                                 \
        oIJ.z = fmaf(p6,q6, fmaf(-p1,q1, oIJ.y));                                 \
        oIJ.w = fmaf(p7,q7, fmaf(-p2,q2, oIJ.z));                                 \
        *(float4*)&sh[BUF][0][r][4*xq] = oI;                                      \
        *(float4*)&sh[BUF][1][r][4*xq] = oJ;                                      \
        *(float4*)&sh[BUF][2][r][4*xq] = oII;                                     \
        *(float4*)&sh[BUF][3][r][4*xq] = oJJ;                                     \
        *(float4*)&sh[BUF][4][r][4*xq] = oIJ;                                     \
    } while (0)

    // z rings + incremental z-window sums, for 2 y-outputs x 5 channels.
    float ring[2][5][5];
    float Sz[2][5];
#pragma unroll
    for (int o = 0; o < 2; ++o)
#pragma unroll
        for (int ch = 0; ch < 5; ++ch) {
            Sz[o][ch] = 0.f;
#pragma unroll
            for (int s = 0; s < 5; ++s) ring[o][ch][s] = 0.f;
        }
    float acc = 0.f;

    if (bAct) PREF(z0 - 2);

    for (int base = 0; base < ITERS; base += 5) {
#pragma unroll
        for (int s = 0; s < 5; ++s) {
            const int it  = base + s;
            const int buf = it & 1;

            if (bAct) {
                BSTAGE(buf);
                if (it < ITERS - 1) PREF(z0 - 1 + it);
            }
            __syncthreads();

            // Stage D: y-window sums for 2 adjacent outputs, then z ring update
            float ysum[2][5];
#pragma unroll
            for (int ch = 0; ch < 5; ++ch) {
                const float v0 = sh[buf][ch][dy + 0][dx];
                const float v1 = sh[buf][ch][dy + 1][dx];
                const float v2 = sh[buf][ch][dy + 2][dx];
                const float v3 = sh[buf][ch][dy + 3][dx];
                const float v4 = sh[buf][ch][dy + 4][dx];
                const float v5 = sh[buf][ch][dy + 5][dx];
                const float y0 = v0 + v1 + v2 + v3 + v4;
                ysum[0][ch] = y0;
                ysum[1][ch] = y0 - v0 + v5;
            }
#pragma unroll
            for (int o = 0; o < 2; ++o)
#pragma unroll
                for (int ch = 0; ch < 5; ++ch) {
                    Sz[o][ch] += ysum[o][ch] - ring[o][ch][s];
                    ring[o][ch][s] = ysum[o][ch];
                }

            if (it >= 4) {
                const float INV = 1.0f / 125.0f;
#pragma unroll
                for (int o = 0; o < 2; ++o) {
                    const float uI = Sz[o][0] * INV, uJ = Sz[o][1] * INV;
                    const float cross = fmaf(-uI, uJ, Sz[o][4] * INV);
                    const float vi    = fmaf(-uI, uI, Sz[o][2] * INV);
                    const float vj    = fmaf(-uJ, uJ, Sz[o][3] * INV);
                    acc += __fdividef(cross * cross, fmaf(vi, vj, 1e-5f));
                }
            }
        }
    }

#undef PREF
#undef BSTAGE

    // ---- Reduction ----
#pragma unroll
    for (int o = 16; o > 0; o >>= 1)
        acc += __shfl_xor_sync(0xffffffffu, acc, o);
    if ((tid & 31) == 0)
        atomicAdd(&blockAcc, acc);
    __syncthreads();
    if (tid == 0) {
        const float INVN = 1.0f / (float)((long)NB * DSZ * DSZ * DSZ);
        atomicAdd(out, -blockAcc * INVN);
    }
}

extern "C" void kernel_launch(void* const* d_in, const int* in_sizes, int n_in,
                              void* d_out, int out_size)
{
    const float* pred = (const float*)d_in[0];
    const float* targ = (const float*)d_in[1];
    float* out = (float*)d_out;

    hx_zero_out<<<1, 1>>>(out);

    dim3 grid(DSZ / TX, DSZ / TY, NB * (DSZ / ZCH));   // 3 x 24 x 4 = 288 blocks
    lncc_kernel<<<grid, NT>>>(pred, targ, out);
}

// round 6
// speedup vs baseline: 1.9325x; 1.0248x over previous
#include <cuda_runtime.h>

#define DSZ 192
#define PL  (DSZ * DSZ)          // floats per z-plane
#define NB  2
#define TX  32                   // tile width (x)
#define TY  16                   // tile height (y outputs per plane)
#define ZCH 96                   // z outputs per block
#define NT  256                  // threads per block
#define HR  20                   // x-sum rows incl. y halo = TY + 4
#define ITERS (ZCH + 4)          // 100 planes per block

__global__ void hx_zero_out(float* out) { out[0] = 0.0f; }

__global__ __launch_bounds__(NT, 2)
void lncc_kernel(const float* __restrict__ pred,
                 const float* __restrict__ targ,
                 float* __restrict__ out)
{
    // x-filtered window sums, channel-major, double buffered.
    // channels: 0=I, 1=J, 2=I2, 3=J2, 4=IJ.  Row = 32 floats = 128 B.
    __shared__ float sh[2][5][HR][TX];
    __shared__ float blockAcc;

    const int tid = threadIdx.x;
    const int bx = blockIdx.x, by = blockIdx.y;
    const int batch = blockIdx.z >> 1;
    const int z0    = (blockIdx.z & 1) * ZCH;

    if (tid == 0) blockAcc = 0.0f;

    // ---- Stage B mapping: 160 active threads = 20 rows x 8 x-chunks of 4 ----
    const int  r    = tid >> 3;                 // 0..31 (active < 20)
    const int  xq   = tid & 7;
    const bool bAct = (r < HR);
    const int  gy   = by * TY + r - 2;
    const bool rowok = bAct && ((unsigned)gy < (unsigned)DSZ);
    const int  gx0  = bx * TX + 4 * xq - 2;     // leftmost of 8 input floats (even)
    const bool c0 = rowok && ((unsigned)(gx0    ) <= 190u);
    const bool c1 = rowok && ((unsigned)(gx0 + 2) <= 190u);
    const bool c2 = rowok && ((unsigned)(gx0 + 4) <= 190u);
    const bool c3 = rowok && ((unsigned)(gx0 + 6) <= 190u);

    const int gyc = gy < 0 ? 0 : (gy > DSZ - 1 ? DSZ - 1 : gy);
    const long off = (long)batch * DSZ * PL + (long)gyc * DSZ + gx0;
    const float* pB = pred + off;
    const float* tB = targ + off;

    // ---- Stage D mapping: each thread owns 2 adjacent y outputs ----
    const int dy = (tid >> 5) * 2;              // 0,2,...,14
    const int dx = tid & 31;

    float2 pa0, pa1, pa2, pa3, ta0, ta1, ta2, ta3;   // prefetch regs
    const float2 Z2 = make_float2(0.f, 0.f);

#define PREF(ZI) do {                                                     \
        const int  zi_  = (ZI);                                           \
        const bool zok_ = (unsigned)zi_ < (unsigned)DSZ;                  \
        const long po_  = (long)(zok_ ? zi_ : 0) * PL;                    \
        pa0 = (zok_ && c0) ? *(const float2*)(pB + po_    ) : Z2;         \
        pa1 = (zok_ && c1) ? *(const float2*)(pB + po_ + 2) : Z2;         \
        pa2 = (zok_ && c2) ? *(const float2*)(pB + po_ + 4) : Z2;         \
        pa3 = (zok_ && c3) ? *(const float2*)(pB + po_ + 6) : Z2;         \
        ta0 = (zok_ && c0) ? *(const float2*)(tB + po_    ) : Z2;         \
        ta1 = (zok_ && c1) ? *(const float2*)(tB + po_ + 2) : Z2;         \
        ta2 = (zok_ && c2) ? *(const float2*)(tB + po_ + 4) : Z2;         \
        ta3 = (zok_ && c3) ? *(const float2*)(tB + po_ + 6) : Z2;         \
    } while (0)

#define BSTAGE(BUF) do {                                                          \
        const float p0=pa0.x,p1=pa0.y,p2=pa1.x,p3=pa1.y,p4=pa2.x,p5=pa2.y,p6=pa3.x,p7=pa3.y; \
        const float q0=ta0.x,q1=ta0.y,q2=ta1.x,q3=ta1.y,q4=ta2.x,q5=ta2.y,q6=ta3.x,q7=ta3.y; \
        float4 oI, oJ, oII, oJJ, oIJ;                                             \
        oI.x = p0 + p1 + p2 + p3 + p4;                                            \
        oI.y = oI.x - p0 + p5;  oI.z = oI.y - p1 + p6;  oI.w = oI.z - p2 + p7;    \
        oJ.x = q0 + q1 + q2 + q3 + q4;                                            \
        oJ.y = oJ.x - q0 + q5;  oJ.z = oJ.y - q1 + q6;  oJ.w = oJ.z - q2 + q7;    \
        oII.x = fmaf(p4,p4, fmaf(p3,p3, fmaf(p2,p2, fmaf(p1,p1, p0*p0))));        \
        oII.y = fmaf(p5,p5, fmaf(-p0,p0, oII.x));                                 \
        oII.z = fmaf(p6,p6, fmaf(-p1,p1, oII.y));                                 \
        oII.w = fmaf(p7,p7, fmaf(-p2,p2, oII.z));                                 \
        oJJ.x = fmaf(q4,q4, fmaf(q3,q3, fmaf(q2,q2, fmaf(q1,q1, q0*q0))));        \
        oJJ.y = fmaf(q5,q5, fmaf(-q0,q0, oJJ.x));                                 \
        oJJ.z = fmaf(q6,q6, fmaf(-q1,q1, oJJ.y));                                 \
        oJJ.w = fmaf(q7,q7, fmaf(-q2,q2, oJJ.z));                                 \
        oIJ.x = fmaf(p4,q4, fmaf(p3,q3, fmaf(p2,q2, fmaf(p1,q1, p0*q0))));        \
        oIJ.y = fmaf(p5,q5, fmaf(-p0,q0, oIJ.x));                                 \
        oIJ.z = fmaf(p6,q6, fmaf(-p1,q1, oIJ.y));                                 \
        oIJ.w = fmaf(p7,q7, fmaf(-p2,q2, oIJ.z));                                 \
        *(float4*)&sh[BUF][0][r][4*xq] = oI;                                      \
        *(float4*)&sh[BUF][1][r][4*xq] = oJ;                                      \
        *(float4*)&sh[BUF][2][r][4*xq] = oII;                                     \
        *(float4*)&sh[BUF][3][r][4*xq] = oJJ;                                     \
        *(float4*)&sh[BUF][4][r][4*xq] = oIJ;                                     \
    } while (0)

    // z rings + incremental z-window sums, for 2 y-outputs x 5 channels.
    float ring[2][5][5];
    float Sz[2][5];
#pragma unroll
    for (int o = 0; o < 2; ++o)
#pragma unroll
        for (int ch = 0; ch < 5; ++ch) {
            Sz[o][ch] = 0.f;
#pragma unroll
            for (int s = 0; s < 5; ++s) ring[o][ch][s] = 0.f;
        }
    float acc = 0.f;

    if (bAct) PREF(z0 - 2);

    for (int base = 0; base < ITERS; base += 5) {
#pragma unroll
        for (int s = 0; s < 5; ++s) {
            const int it  = base + s;
            const int buf = it & 1;

            if (bAct) {
                BSTAGE(buf);
                if (it < ITERS - 1) PREF(z0 - 1 + it);
            }
            __syncthreads();

            // Stage D: y-window sums for 2 adjacent outputs, then z ring update
            float ysum[2][5];
#pragma unroll
            for (int ch = 0; ch < 5; ++ch) {
                const float v0 = sh[buf][ch][dy + 0][dx];
                const float v1 = sh[buf][ch][dy + 1][dx];
                const float v2 = sh[buf][ch][dy + 2][dx];
                const float v3 = sh[buf][ch][dy + 3][dx];
                const float v4 = sh[buf][ch][dy + 4][dx];
                const float v5 = sh[buf][ch][dy + 5][dx];
                const float y0 = v0 + v1 + v2 + v3 + v4;
                ysum[0][ch] = y0;
                ysum[1][ch] = y0 - v0 + v5;
            }
#pragma unroll
            for (int o = 0; o < 2; ++o)
#pragma unroll
                for (int ch = 0; ch < 5; ++ch) {
                    Sz[o][ch] += ysum[o][ch] - ring[o][ch][s];
                    ring[o][ch][s] = ysum[o][ch];
                }

            if (it >= 4) {
                const float INV = 1.0f / 125.0f;
#pragma unroll
                for (int o = 0; o < 2; ++o) {
                    const float uI = Sz[o][0] * INV, uJ = Sz[o][1] * INV;
                    const float cross = fmaf(-uI, uJ, Sz[o][4] * INV);
                    const float vi    = fmaf(-uI, uI, Sz[o][2] * INV);
                    const float vj    = fmaf(-uJ, uJ, Sz[o][3] * INV);
                    acc += __fdividef(cross * cross, fmaf(vi, vj, 1e-5f));
                }
            }
        }
    }

#undef PREF
#undef BSTAGE

    // ---- Reduction ----
#pragma unroll
    for (int o = 16; o > 0; o >>= 1)
        acc += __shfl_xor_sync(0xffffffffu, acc, o);
    if ((tid & 31) == 0)
        atomicAdd(&blockAcc, acc);
    __syncthreads();
    if (tid == 0) {
        const float INVN = 1.0f / (float)((long)NB * DSZ * DSZ * DSZ);
        atomicAdd(out, -blockAcc * INVN);
    }
}

extern "C" void kernel_launch(void* const* d_in, const int* in_sizes, int n_in,
                              void* d_out, int out_size)
{
    const float* pred = (const float*)d_in[0];
    const float* targ = (const float*)d_in[1];
    float* out = (float*)d_out;

    hx_zero_out<<<1, 1>>>(out);

    dim3 grid(DSZ / TX, DSZ / TY, NB * (DSZ / ZCH));   // 6 x 12 x 4 = 288 blocks
    lncc_kernel<<<grid, NT>>>(pred, targ, out);
}

// round 7
// speedup vs baseline: 2.1075x; 1.0906x over previous
#include <cuda_runtime.h>

#define DSZ 192
#define PL  (DSZ * DSZ)
#define NB  2
#define TX  32                   // tile width (x)
#define TY  16                   // tile height (y)
#define ZCH 96                   // z outputs per block
#define NT  256
#define HR  20                   // TY + 4
#define PAIRS 50                 // 100 planes per block, 2 per iteration

// dynamic smem: [pairbuf 2][plane 2][ch 5][row HR][x TX]
#define SH(pb,pl,ch,rw,x) shm[((((pb)*2+(pl))*5+(ch))*HR + (rw))*TX + (x)]
#define SMEM_BYTES (2*2*5*HR*TX*4)

__global__ void hx_zero_out(float* out) { out[0] = 0.0f; }

__global__ __launch_bounds__(NT, 2)
void lncc_kernel(const float* __restrict__ pred,
                 const float* __restrict__ targ,
                 float* __restrict__ out)
{
    extern __shared__ float shm[];
    __shared__ float blockAcc;

    const int tid = threadIdx.x;
    const int bx = blockIdx.x, by = blockIdx.y;
    const int batch = blockIdx.z >> 1;
    const int z0    = (blockIdx.z & 1) * ZCH;

    if (tid == 0) blockAcc = 0.0f;

    // ---- Stage B mapping: 160 active threads = 20 rows x 8 x-chunks of 4 ----
    const int  r    = tid >> 3;
    const int  xq   = tid & 7;
    const bool bAct = (r < HR);
    const int  gy   = by * TY + r - 2;
    const bool rowok = bAct && ((unsigned)gy < (unsigned)DSZ);
    const int  gx0  = bx * TX + 4 * xq - 2;
    const bool c0 = rowok && ((unsigned)(gx0    ) <= 190u);
    const bool c1 = rowok && ((unsigned)(gx0 + 2) <= 190u);
    const bool c2 = rowok && ((unsigned)(gx0 + 4) <= 190u);
    const bool c3 = rowok && ((unsigned)(gx0 + 6) <= 190u);

    const int gyc = gy < 0 ? 0 : (gy > DSZ - 1 ? DSZ - 1 : gy);
    const long off = (long)batch * DSZ * PL + (long)gyc * DSZ + gx0;
    const float* pB = pred + off;
    const float* tB = targ + off;

    // ---- Stage D mapping: each thread owns 2 adjacent y outputs ----
    const int dy = (tid >> 5) * 2;
    const int dx = tid & 31;

    float2 Lp[2][4], Lt[2][4];       // prefetched inputs for a plane pair
    const float2 Z2 = make_float2(0.f, 0.f);

#define LOADP(PLN, ZI) do {                                               \
        const int  zi_  = (ZI);                                           \
        const bool zok_ = (unsigned)zi_ < (unsigned)DSZ;                  \
        const long po_  = (long)(zok_ ? zi_ : 0) * PL;                    \
        Lp[PLN][0] = (zok_ && c0) ? *(const float2*)(pB + po_    ) : Z2;  \
        Lp[PLN][1] = (zok_ && c1) ? *(const float2*)(pB + po_ + 2) : Z2;  \
        Lp[PLN][2] = (zok_ && c2) ? *(const float2*)(pB + po_ + 4) : Z2;  \
        Lp[PLN][3] = (zok_ && c3) ? *(const float2*)(pB + po_ + 6) : Z2;  \
        Lt[PLN][0] = (zok_ && c0) ? *(const float2*)(tB + po_    ) : Z2;  \
        Lt[PLN][1] = (zok_ && c1) ? *(const float2*)(tB + po_ + 2) : Z2;  \
        Lt[PLN][2] = (zok_ && c2) ? *(const float2*)(tB + po_ + 4) : Z2;  \
        Lt[PLN][3] = (zok_ && c3) ? *(const float2*)(tB + po_ + 6) : Z2;  \
    } while (0)

#define BST(PLN, PB) do {                                                          \
        const float p0=Lp[PLN][0].x,p1=Lp[PLN][0].y,p2=Lp[PLN][1].x,p3=Lp[PLN][1].y; \
        const float p4=Lp[PLN][2].x,p5=Lp[PLN][2].y,p6=Lp[PLN][3].x,p7=Lp[PLN][3].y; \
        const float q0=Lt[PLN][0].x,q1=Lt[PLN][0].y,q2=Lt[PLN][1].x,q3=Lt[PLN][1].y; \
        const float q4=Lt[PLN][2].x,q5=Lt[PLN][2].y,q6=Lt[PLN][3].x,q7=Lt[PLN][3].y; \
        float4 oI, oJ, oII, oJJ, oIJ;                                              \
        oI.x = p0 + p1 + p2 + p3 + p4;                                             \
        oI.y = oI.x - p0 + p5;  oI.z = oI.y - p1 + p6;  oI.w = oI.z - p2 + p7;     \
        oJ.x = q0 + q1 + q2 + q3 + q4;                                             \
        oJ.y = oJ.x - q0 + q5;  oJ.z = oJ.y - q1 + q6;  oJ.w = oJ.z - q2 + q7;     \
        oII.x = fmaf(p4,p4, fmaf(p3,p3, fmaf(p2,p2, fmaf(p1,p1, p0*p0))));         \
        oII.y = fmaf(p5,p5, fmaf(-p0,p0, oII.x));                                  \
        oII.z = fmaf(p6,p6, fmaf(-p1,p1, oII.y));                                  \
        oII.w = fmaf(p7,p7, fmaf(-p2,p2, oII.z));                                  \
        oJJ.x = fmaf(q4,q4, fmaf(q3,q3, fmaf(q2,q2, fmaf(q1,q1, q0*q0))));         \
        oJJ.y = fmaf(q5,q5, fmaf(-q0,q0, oJJ.x));                                  \
        oJJ.z = fmaf(q6,q6, fmaf(-q1,q1, oJJ.y));                                  \
        oJJ.w = fmaf(q7,q7, fmaf(-q2,q2, oJJ.z));                                  \
        oIJ.x = fmaf(p4,q4, fmaf(p3,q3, fmaf(p2,q2, fmaf(p1,q1, p0*q0))));         \
        oIJ.y = fmaf(p5,q5, fmaf(-p0,q0, oIJ.x));                                  \
        oIJ.z = fmaf(p6,q6, fmaf(-p1,q1, oIJ.y));                                  \
        oIJ.w = fmaf(p7,q7, fmaf(-p2,q2, oIJ.z));                                  \
        *(float4*)&SH(PB, PLN, 0, r, 4*xq) = oI;                                   \
        *(float4*)&SH(PB, PLN, 1, r, 4*xq) = oJ;                                   \
        *(float4*)&SH(PB, PLN, 2, r, 4*xq) = oII;                                  \
        *(float4*)&SH(PB, PLN, 3, r, 4*xq) = oJJ;                                  \
        *(float4*)&SH(PB, PLN, 4, r, 4*xq) = oIJ;                                  \
    } while (0)

    // z rings + incremental sums for 2 y-outputs x 5 channels
    float ring[2][5][5];
    float Sz[2][5];
#pragma unroll
    for (int o = 0; o < 2; ++o)
#pragma unroll
        for (int ch = 0; ch < 5; ++ch) {
            Sz[o][ch] = 0.f;
#pragma unroll
            for (int s = 0; s < 5; ++s) ring[o][ch][s] = 0.f;
        }
    float acc = 0.f;

    // D stage for one plane (static SLOT), it_ = plane index 0..99
#define DST(PB, PLN, SLOT, IT) do {                                               \
        float ysum[2][5];                                                         \
        _Pragma("unroll")                                                         \
        for (int ch = 0; ch < 5; ++ch) {                                          \
            const float v0 = SH(PB, PLN, ch, dy + 0, dx);                         \
            const float v1 = SH(PB, PLN, ch, dy + 1, dx);                         \
            const float v2 = SH(PB, PLN, ch, dy + 2, dx);                         \
            const float v3 = SH(PB, PLN, ch, dy + 3, dx);                         \
            const float v4 = SH(PB, PLN, ch, dy + 4, dx);                         \
            const float v5 = SH(PB, PLN, ch, dy + 5, dx);                         \
            const float y0 = v0 + v1 + v2 + v3 + v4;                              \
            ysum[0][ch] = y0;                                                     \
            ysum[1][ch] = y0 - v0 + v5;                                           \
        }                                                                         \
        _Pragma("unroll")                                                         \
        for (int o = 0; o < 2; ++o)                                               \
            _Pragma("unroll")                                                     \
            for (int ch = 0; ch < 5; ++ch) {                                      \
                Sz[o][ch] += ysum[o][ch] - ring[o][ch][SLOT];                     \
                ring[o][ch][SLOT] = ysum[o][ch];                                  \
            }                                                                     \
        if ((IT) >= 4) {                                                          \
            const float INV = 1.0f / 125.0f;                                      \
            _Pragma("unroll")                                                     \
            for (int o = 0; o < 2; ++o) {                                         \
                const float uI = Sz[o][0] * INV, uJ = Sz[o][1] * INV;             \
                const float cross = fmaf(-uI, uJ, Sz[o][4] * INV);                \
                const float vi    = fmaf(-uI, uI, Sz[o][2] * INV);                \
                const float vj    = fmaf(-uJ, uJ, Sz[o][3] * INV);                \
                acc += __fdividef(cross * cross, fmaf(vi, vj, 1e-5f));            \
            }                                                                     \
        }                                                                         \
    } while (0)

    // preload pair 0 (planes z0-2, z0-1)
    if (bAct) { LOADP(0, z0 - 2); LOADP(1, z0 - 1); }

    for (int g = 0; g < PAIRS / 5; ++g) {          // 10 groups of 5 pairs
#pragma unroll
        for (int j = 0; j < 5; ++j) {
            const int pi = g * 5 + j;              // pair index 0..49
            const int pb = (g + j) & 1;            // (g*5+j) & 1
            const int it0 = 2 * pi;                // first plane index of pair

            if (bAct) {
                BST(0, pb);
                BST(1, pb);
                if (pi < PAIRS - 1) {              // prefetch next pair
                    LOADP(0, z0 + 2 * pi);         // z0-2+2*(pi+1)
                    LOADP(1, z0 + 2 * pi + 1);
                }
            }
            __syncthreads();

            DST(pb, 0, (2 * j) % 5,     it0);
            DST(pb, 1, (2 * j + 1) % 5, it0 + 1);
        }
    }

#undef LOADP
#undef BST
#undef DST

    // ---- Reduction ----
#pragma unroll
    for (int o = 16; o > 0; o >>= 1)
        acc += __shfl_xor_sync(0xffffffffu, acc, o);
    if ((tid & 31) == 0)
        atomicAdd(&blockAcc, acc);
    __syncthreads();
    if (tid == 0) {
        const float INVN = 1.0f / (float)((long)NB * DSZ * DSZ * DSZ);
        atomicAdd(out, -blockAcc * INVN);
    }
}

extern "C" void kernel_launch(void* const* d_in, const int* in_sizes, int n_in,
                              void* d_out, int out_size)
{
    const float* pred = (const float*)d_in[0];
    const float* targ = (const float*)d_in[1];
    float* out = (float*)d_out;

    cudaFuncSetAttribute(lncc_kernel,
                         cudaFuncAttributeMaxDynamicSharedMemorySize, SMEM_BYTES);

    hx_zero_out<<<1, 1>>>(out);

    dim3 grid(DSZ / TX, DSZ / TY, NB * (DSZ / ZCH));   // 6 x 12 x 4 = 288 blocks
    lncc_kernel<<<grid, NT, SMEM_BYTES>>>(pred, targ, out);
}

// round 8
// speedup vs baseline: 2.4118x; 1.1444x over previous
#include <cuda_runtime.h>
#include <cuda_fp16.h>

#define DSZ 192
#define PL  (DSZ * DSZ)
#define NB  2
#define TX  32                   // tile width (x)
#define TY  16                   // tile height (y)
#define ZCH 96                   // z outputs per block
#define NT  256
#define HR  20                   // TY + 4
#define PAIRS 50                 // 100 planes per block, 2 per iteration

// element index within one [slot][row][x] array (4 slots = 2 pairbufs x 2 planes)
#define IDX(slot,rw,x) (((slot)*HR + (rw))*TX + (x))
// dynamic smem: shIJ half2[4*HR*TX] | shQQ half2[4*HR*TX] | shE half[4*HR*TX]
#define NELT (4*HR*TX)
#define SMEM_BYTES (NELT*4 + NELT*4 + NELT*2)

__global__ void hx_zero_out(float* out) { out[0] = 0.0f; }

__global__ __launch_bounds__(NT, 2)
void lncc_kernel(const float* __restrict__ pred,
                 const float* __restrict__ targ,
                 float* __restrict__ out)
{
    extern __shared__ char shm[];
    __half2* const shIJ = (__half2*)shm;                    // (I, J)
    __half2* const shQQ = shIJ + NELT;                      // (I2, J2)
    __half*  const shE  = (__half*)(shQQ + NELT);           // IJ
    __shared__ float blockAcc;

    const int tid = threadIdx.x;
    const int bx = blockIdx.x, by = blockIdx.y;
    const int batch = blockIdx.z >> 1;
    const int z0    = (blockIdx.z & 1) * ZCH;

    if (tid == 0) blockAcc = 0.0f;

    // ---- Stage B mapping: 160 active threads = 20 rows x 8 x-chunks of 4 ----
    const int  r    = tid >> 3;
    const int  xq   = tid & 7;
    const bool bAct = (r < HR);
    const int  gy   = by * TY + r - 2;
    const bool rowok = bAct && ((unsigned)gy < (unsigned)DSZ);
    const int  gx0  = bx * TX + 4 * xq - 2;
    const bool c0 = rowok && ((unsigned)(gx0    ) <= 190u);
    const bool c1 = rowok && ((unsigned)(gx0 + 2) <= 190u);
    const bool c2 = rowok && ((unsigned)(gx0 + 4) <= 190u);
    const bool c3 = rowok && ((unsigned)(gx0 + 6) <= 190u);

    const int gyc = gy < 0 ? 0 : (gy > DSZ - 1 ? DSZ - 1 : gy);
    const long off = (long)batch * DSZ * PL + (long)gyc * DSZ + gx0;
    const float* pB = pred + off;
    const float* tB = targ + off;

    // ---- Stage D mapping: each thread owns 2 adjacent y outputs ----
    const int dy = (tid >> 5) * 2;
    const int dx = tid & 31;

    float2 Lp[2][4], Lt[2][4];       // prefetched inputs for a plane pair
    const float2 Z2 = make_float2(0.f, 0.f);

#define LOADP(PLN, ZI) do {                                               \
        const int  zi_  = (ZI);                                           \
        const bool zok_ = (unsigned)zi_ < (unsigned)DSZ;                  \
        const long po_  = (long)(zok_ ? zi_ : 0) * PL;                    \
        Lp[PLN][0] = (zok_ && c0) ? *(const float2*)(pB + po_    ) : Z2;  \
        Lp[PLN][1] = (zok_ && c1) ? *(const float2*)(pB + po_ + 2) : Z2;  \
        Lp[PLN][2] = (zok_ && c2) ? *(const float2*)(pB + po_ + 4) : Z2;  \
        Lp[PLN][3] = (zok_ && c3) ? *(const float2*)(pB + po_ + 6) : Z2;  \
        Lt[PLN][0] = (zok_ && c0) ? *(const float2*)(tB + po_    ) : Z2;  \
        Lt[PLN][1] = (zok_ && c1) ? *(const float2*)(tB + po_ + 2) : Z2;  \
        Lt[PLN][2] = (zok_ && c2) ? *(const float2*)(tB + po_ + 4) : Z2;  \
        Lt[PLN][3] = (zok_ && c3) ? *(const float2*)(tB + po_ + 6) : Z2;  \
    } while (0)

#define BST(PLN, PB) do {                                                          \
        const float p0=Lp[PLN][0].x,p1=Lp[PLN][0].y,p2=Lp[PLN][1].x,p3=Lp[PLN][1].y; \
        const float p4=Lp[PLN][2].x,p5=Lp[PLN][2].y,p6=Lp[PLN][3].x,p7=Lp[PLN][3].y; \
        const float q0=Lt[PLN][0].x,q1=Lt[PLN][0].y,q2=Lt[PLN][1].x,q3=Lt[PLN][1].y; \
        const float q4=Lt[PLN][2].x,q5=Lt[PLN][2].y,q6=Lt[PLN][3].x,q7=Lt[PLN][3].y; \
        float4 oI, oJ, oII, oJJ, oIJ;                                              \
        oI.x = p0 + p1 + p2 + p3 + p4;                                             \
        oI.y = oI.x - p0 + p5;  oI.z = oI.y - p1 + p6;  oI.w = oI.z - p2 + p7;     \
        oJ.x = q0 + q1 + q2 + q3 + q4;                                             \
        oJ.y = oJ.x - q0 + q5;  oJ.z = oJ.y - q1 + q6;  oJ.w = oJ.z - q2 + q7;     \
        oII.x = fmaf(p4,p4, fmaf(p3,p3, fmaf(p2,p2, fmaf(p1,p1, p0*p0))));         \
        oII.y = fmaf(p5,p5, fmaf(-p0,p0, oII.x));                                  \
        oII.z = fmaf(p6,p6, fmaf(-p1,p1, oII.y));                                  \
        oII.w = fmaf(p7,p7, fmaf(-p2,p2, oII.z));                                  \
        oJJ.x = fmaf(q4,q4, fmaf(q3,q3, fmaf(q2,q2, fmaf(q1,q1, q0*q0))));         \
        oJJ.y = fmaf(q5,q5, fmaf(-q0,q0, oJJ.x));                                  \
        oJJ.z = fmaf(q6,q6, fmaf(-q1,q1, oJJ.y));                                  \
        oJJ.w = fmaf(q7,q7, fmaf(-q2,q2, oJJ.z));                                  \
        oIJ.x = fmaf(p4,q4, fmaf(p3,q3, fmaf(p2,q2, fmaf(p1,q1, p0*q0))));         \
        oIJ.y = fmaf(p5,q5, fmaf(-p0,q0, oIJ.x));                                  \
        oIJ.z = fmaf(p6,q6, fmaf(-p1,q1, oIJ.y));                                  \
        oIJ.w = fmaf(p7,q7, fmaf(-p2,q2, oIJ.z));                                  \
        const int slot_ = (PB)*2 + (PLN);                                          \
        uint4 uIJ, uQQ; uint2 uE; __half2 t_;                                      \
        t_ = __floats2half2_rn(oI.x,  oJ.x ); uIJ.x = *(unsigned*)&t_;             \
        t_ = __floats2half2_rn(oI.y,  oJ.y ); uIJ.y = *(unsigned*)&t_;             \
        t_ = __floats2half2_rn(oI.z,  oJ.z ); uIJ.z = *(unsigned*)&t_;             \
        t_ = __floats2half2_rn(oI.w,  oJ.w ); uIJ.w = *(unsigned*)&t_;             \
        t_ = __floats2half2_rn(oII.x, oJJ.x); uQQ.x = *(unsigned*)&t_;             \
        t_ = __floats2half2_rn(oII.y, oJJ.y); uQQ.y = *(unsigned*)&t_;             \
        t_ = __floats2half2_rn(oII.z, oJJ.z); uQQ.z = *(unsigned*)&t_;             \
        t_ = __floats2half2_rn(oII.w, oJJ.w); uQQ.w = *(unsigned*)&t_;             \
        t_ = __floats2half2_rn(oIJ.x, oIJ.y); uE.x  = *(unsigned*)&t_;             \
        t_ = __floats2half2_rn(oIJ.z, oIJ.w); uE.y  = *(unsigned*)&t_;             \
        *(uint4*)&shIJ[IDX(slot_, r, 4*xq)] = uIJ;                                 \
        *(uint4*)&shQQ[IDX(slot_, r, 4*xq)] = uQQ;                                 \
        *(uint2*)&shE [IDX(slot_, r, 4*xq)] = uE;                                  \
    } while (0)

    // z rings + incremental sums for 2 y-outputs x 5 channels (fp32)
    float ring[2][5][5];
    float Sz[2][5];
#pragma unroll
    for (int o = 0; o < 2; ++o)
#pragma unroll
        for (int ch = 0; ch < 5; ++ch) {
            Sz[o][ch] = 0.f;
#pragma unroll
            for (int s = 0; s < 5; ++s) ring[o][ch][s] = 0.f;
        }
    float acc = 0.f;

    // D stage for one plane; fp16 loads, fp32 accumulation
#define DST(PB, PLN, SLOT, IT) do {                                               \
        const int slot_ = (PB)*2 + (PLN);                                         \
        float yI0=0.f,yJ0=0.f,yII0=0.f,yJJ0=0.f,yE0=0.f;  /* rows 0..4 */         \
        float2 v0ij, v0qq; float v0e;                                             \
        _Pragma("unroll")                                                         \
        for (int j = 0; j < 5; ++j) {                                             \
            const float2 ij = __half22float2(shIJ[IDX(slot_, dy + j, dx)]);       \
            const float2 qq = __half22float2(shQQ[IDX(slot_, dy + j, dx)]);       \
            const float  e  = __half2float (shE [IDX(slot_, dy + j, dx)]);        \
            if (j == 0) { v0ij = ij; v0qq = qq; v0e = e; }                        \
            yI0 += ij.x; yJ0 += ij.y; yII0 += qq.x; yJJ0 += qq.y; yE0 += e;       \
        }                                                                         \
        const float2 ij5 = __half22float2(shIJ[IDX(slot_, dy + 5, dx)]);          \
        const float2 qq5 = __half22float2(shQQ[IDX(slot_, dy + 5, dx)]);          \
        const float  e5  = __half2float (shE [IDX(slot_, dy + 5, dx)]);           \
        float ysum[2][5];                                                         \
        ysum[0][0]=yI0;  ysum[1][0]=yI0  - v0ij.x + ij5.x;                        \
        ysum[0][1]=yJ0;  ysum[1][1]=yJ0  - v0ij.y + ij5.y;                        \
        ysum[0][2]=yII0; ysum[1][2]=yII0 - v0qq.x + qq5.x;                        \
        ysum[0][3]=yJJ0; ysum[1][3]=yJJ0 - v0qq.y + qq5.y;                        \
        ysum[0][4]=yE0;  ysum[1][4]=yE0  - v0e    + e5;                           \
        _Pragma("unroll")                                                         \
        for (int o = 0; o < 2; ++o)                                               \
            _Pragma("unroll")                                                     \
            for (int ch = 0; ch < 5; ++ch) {                                      \
                Sz[o][ch] += ysum[o][ch] - ring[o][ch][SLOT];                     \
                ring[o][ch][SLOT] = ysum[o][ch];                                  \
            }                                                                     \
        if ((IT) >= 4) {                                                          \
            const float INV = 1.0f / 125.0f;                                      \
            _Pragma("unroll")                                                     \
            for (int o = 0; o < 2; ++o) {                                         \
                const float uI = Sz[o][0] * INV, uJ = Sz[o][1] * INV;             \
                const float cross = fmaf(-uI, uJ, Sz[o][4] * INV);                \
                const float vi    = fmaf(-uI, uI, Sz[o][2] * INV);                \
                const float vj    = fmaf(-uJ, uJ, Sz[o][3] * INV);                \
                acc += __fdividef(cross * cross, fmaf(vi, vj, 1e-5f));            \
            }                                                                     \
        }                                                                         \
    } while (0)

    // preload pair 0 (planes z0-2, z0-1)
    if (bAct) { LOADP(0, z0 - 2); LOADP(1, z0 - 1); }

    for (int g = 0; g < PAIRS / 5; ++g) {          // 10 groups of 5 pairs
#pragma unroll
        for (int j = 0; j < 5; ++j) {
            const int pi = g * 5 + j;              // pair index 0..49
            const int pb = (g + j) & 1;
            const int it0 = 2 * pi;                // first plane index of pair

            if (bAct) {
                BST(0, pb);
                BST(1, pb);
                if (pi < PAIRS - 1) {              // prefetch next pair
                    LOADP(0, z0 + 2 * pi);
                    LOADP(1, z0 + 2 * pi + 1);
                }
            }
            __syncthreads();

            DST(pb, 0, (2 * j) % 5,     it0);
            DST(pb, 1, (2 * j + 1) % 5, it0 + 1);
        }
    }

#undef LOADP
#undef BST
#undef DST

    // ---- Reduction ----
#pragma unroll
    for (int o = 16; o > 0; o >>= 1)
        acc += __shfl_xor_sync(0xffffffffu, acc, o);
    if ((tid & 31) == 0)
        atomicAdd(&blockAcc, acc);
    __syncthreads();
    if (tid == 0) {
        const float INVN = 1.0f / (float)((long)NB * DSZ * DSZ * DSZ);
        atomicAdd(out, -blockAcc * INVN);
    }
}

extern "C" void kernel_launch(void* const* d_in, const int* in_sizes, int n_in,
                              void* d_out, int out_size)
{
    const float* pred = (const float*)d_in[0];
    const float* targ = (const float*)d_in[1];
    float* out = (float*)d_out;

    cudaFuncSetAttribute(lncc_kernel,
                         cudaFuncAttributeMaxDynamicSharedMemorySize, SMEM_BYTES);

    hx_zero_out<<<1, 1>>>(out);

    dim3 grid(DSZ / TX, DSZ / TY, NB * (DSZ / ZCH));   // 6 x 12 x 4 = 288 blocks
    lncc_kernel<<<grid, NT, SMEM_BYTES>>>(pred, targ, out);
}

// round 9
// speedup vs baseline: 2.5900x; 1.0739x over previous
#include <cuda_runtime.h>
#include <cuda_fp16.h>

#define DSZ 192
#define PL  (DSZ * DSZ)
#define NB  2
#define TX  32                   // tile width (x)
#define TY  16                   // tile height (y)
#define ZCH 96                   // z outputs per block
#define NT  256
#define HR  20                   // TY + 4
#define PAIRS 50                 // 100 planes per block, 2 per iteration

// element index within one [slot][row][x] array (4 slots = 2 pairbufs x 2 planes)
#define IDX(slot,rw,x) (((slot)*HR + (rw))*TX + (x))
#define NELT (4*HR*TX)
// shA: uint2 {half2(I,J), half2(I2,J2)} | shE: half (IJ)
#define SMEM_BYTES (NELT*8 + NELT*2)

__global__ void hx_zero_out(float* out) { out[0] = 0.0f; }

__global__ __launch_bounds__(NT, 2)
void lncc_kernel(const float* __restrict__ pred,
                 const float* __restrict__ targ,
                 float* __restrict__ out)
{
    extern __shared__ char shm[];
    uint2*  const shA = (uint2*)shm;                 // (I,J | I2,J2) packed halves
    __half* const shE = (__half*)(shA + NELT);       // IJ
    __shared__ float blockAcc;

    const int tid = threadIdx.x;
    const int bx = blockIdx.x, by = blockIdx.y;
    const int batch = blockIdx.z >> 1;
    const int z0    = (blockIdx.z & 1) * ZCH;

    if (tid == 0) blockAcc = 0.0f;

    // ---- Stage B mapping: 160 active threads = 20 rows x 8 x-chunks of 4 ----
    const int  r    = tid >> 3;
    const int  xq   = tid & 7;
    const bool bAct = (r < HR);
    const int  gy   = by * TY + r - 2;
    const bool rowok = bAct && ((unsigned)gy < (unsigned)DSZ);
    const int  gx0  = bx * TX + 4 * xq - 2;
    const bool c0 = rowok && ((unsigned)(gx0    ) <= 190u);
    const bool c1 = rowok && ((unsigned)(gx0 + 2) <= 190u);
    const bool c2 = rowok && ((unsigned)(gx0 + 4) <= 190u);
    const bool c3 = rowok && ((unsigned)(gx0 + 6) <= 190u);

    const int gyc = gy < 0 ? 0 : (gy > DSZ - 1 ? DSZ - 1 : gy);
    const long off = (long)batch * DSZ * PL + (long)gyc * DSZ + gx0;
    const float* pB = pred + off;
    const float* tB = targ + off;

    // ---- Stage D mapping: each thread owns 2 adjacent y outputs ----
    const int dy = (tid >> 5) * 2;
    const int dx = tid & 31;

    float2 Lp[2][4], Lt[2][4];       // prefetched inputs for a plane pair
    const float2 Z2 = make_float2(0.f, 0.f);

#define LOADP(PLN, ZI) do {                                               \
        const int  zi_  = (ZI);                                           \
        const bool zok_ = (unsigned)zi_ < (unsigned)DSZ;                  \
        const long po_  = (long)(zok_ ? zi_ : 0) * PL;                    \
        Lp[PLN][0] = (zok_ && c0) ? *(const float2*)(pB + po_    ) : Z2;  \
        Lp[PLN][1] = (zok_ && c1) ? *(const float2*)(pB + po_ + 2) : Z2;  \
        Lp[PLN][2] = (zok_ && c2) ? *(const float2*)(pB + po_ + 4) : Z2;  \
        Lp[PLN][3] = (zok_ && c3) ? *(const float2*)(pB + po_ + 6) : Z2;  \
        Lt[PLN][0] = (zok_ && c0) ? *(const float2*)(tB + po_    ) : Z2;  \
        Lt[PLN][1] = (zok_ && c1) ? *(const float2*)(tB + po_ + 2) : Z2;  \
        Lt[PLN][2] = (zok_ && c2) ? *(const float2*)(tB + po_ + 4) : Z2;  \
        Lt[PLN][3] = (zok_ && c3) ? *(const float2*)(tB + po_ + 6) : Z2;  \
    } while (0)

#define BST(PLN, PB) do {                                                          \
        const float p0=Lp[PLN][0].x,p1=Lp[PLN][0].y,p2=Lp[PLN][1].x,p3=Lp[PLN][1].y; \
        const float p4=Lp[PLN][2].x,p5=Lp[PLN][2].y,p6=Lp[PLN][3].x,p7=Lp[PLN][3].y; \
        const float q0=Lt[PLN][0].x,q1=Lt[PLN][0].y,q2=Lt[PLN][1].x,q3=Lt[PLN][1].y; \
        const float q4=Lt[PLN][2].x,q5=Lt[PLN][2].y,q6=Lt[PLN][3].x,q7=Lt[PLN][3].y; \
        float4 oI, oJ, oII, oJJ, oIJ;                                              \
        oI.x = p0 + p1 + p2 + p3 + p4;                                             \
        oI.y = oI.x - p0 + p5;  oI.z = oI.y - p1 + p6;  oI.w = oI.z - p2 + p7;     \
        oJ.x = q0 + q1 + q2 + q3 + q4;                                             \
        oJ.y = oJ.x - q0 + q5;  oJ.z = oJ.y - q1 + q6;  oJ.w = oJ.z - q2 + q7;     \
        oII.x = fmaf(p4,p4, fmaf(p3,p3, fmaf(p2,p2, fmaf(p1,p1, p0*p0))));         \
        oII.y = fmaf(p5,p5, fmaf(-p0,p0, oII.x));                                  \
        oII.z = fmaf(p6,p6, fmaf(-p1,p1, oII.y));                                  \
        oII.w = fmaf(p7,p7, fmaf(-p2,p2, oII.z));                                  \
        oJJ.x = fmaf(q4,q4, fmaf(q3,q3, fmaf(q2,q2, fmaf(q1,q1, q0*q0))));         \
        oJJ.y = fmaf(q5,q5, fmaf(-q0,q0, oJJ.x));                                  \
        oJJ.z = fmaf(q6,q6, fmaf(-q1,q1, oJJ.y));                                  \
        oJJ.w = fmaf(q7,q7, fmaf(-q2,q2, oJJ.z));                                  \
        oIJ.x = fmaf(p4,q4, fmaf(p3,q3, fmaf(p2,q2, fmaf(p1,q1, p0*q0))));         \
        oIJ.y = fmaf(p5,q5, fmaf(-p0,q0, oIJ.x));                                  \
        oIJ.z = fmaf(p6,q6, fmaf(-p1,q1, oIJ.y));                                  \
        oIJ.w = fmaf(p7,q7, fmaf(-p2,q2, oIJ.z));                                  \
        const int slot_ = (PB)*2 + (PLN);                                          \
        __half2 t_;                                                               \
        uint4 u0, u1; uint2 uE;                                                    \
        t_ = __floats2half2_rn(oI.x,  oJ.x ); u0.x = *(unsigned*)&t_;              \
        t_ = __floats2half2_rn(oII.x, oJJ.x); u0.y = *(unsigned*)&t_;              \
        t_ = __floats2half2_rn(oI.y,  oJ.y ); u0.z = *(unsigned*)&t_;              \
        t_ = __floats2half2_rn(oII.y, oJJ.y); u0.w = *(unsigned*)&t_;              \
        t_ = __floats2half2_rn(oI.z,  oJ.z ); u1.x = *(unsigned*)&t_;              \
        t_ = __floats2half2_rn(oII.z, oJJ.z); u1.y = *(unsigned*)&t_;              \
        t_ = __floats2half2_rn(oI.w,  oJ.w ); u1.z = *(unsigned*)&t_;              \
        t_ = __floats2half2_rn(oII.w, oJJ.w); u1.w = *(unsigned*)&t_;              \
        t_ = __floats2half2_rn(oIJ.x, oIJ.y); uE.x = *(unsigned*)&t_;              \
        t_ = __floats2half2_rn(oIJ.z, oIJ.w); uE.y = *(unsigned*)&t_;              \
        *(uint4*)&shA[IDX(slot_, r, 4*xq)    ] = u0;                               \
        *(uint4*)&shA[IDX(slot_, r, 4*xq) + 2] = u1;                               \
        *(uint2*)&shE[IDX(slot_, r, 4*xq)]     = uE;                               \
    } while (0)

    // z ring: half2 y-sums for (I,J) and (I2,J2), fp32 for IJ
    __half2 ringA[2][5], ringQ[2][5];
    float   ringE[2][5];
    const __half2 HZ = __floats2half2_rn(0.f, 0.f);
#pragma unroll
    for (int o = 0; o < 2; ++o)
#pragma unroll
        for (int s = 0; s < 5; ++s) { ringA[o][s] = HZ; ringQ[o][s] = HZ; ringE[o][s] = 0.f; }
    float acc = 0.f;

    // D stage for one plane: SIMD y-sums + fresh 5-slot z-sums
#define DST(PB, PLN, SLOT, IT) do {                                               \
        const int slot_ = (PB)*2 + (PLN);                                         \
        __half2 a0,a1,a2,a3,a4,a5, q0_,q1_,q2_,q3_,q4_,q5_;                       \
        float e0,e1,e2,e3,e4,e5;                                                  \
        {                                                                         \
            uint2 w;                                                              \
            w = shA[IDX(slot_, dy+0, dx)]; a0=*(__half2*)&w.x; q0_=*(__half2*)&w.y; \
            w = shA[IDX(slot_, dy+1, dx)]; a1=*(__half2*)&w.x; q1_=*(__half2*)&w.y; \
            w = shA[IDX(slot_, dy+2, dx)]; a2=*(__half2*)&w.x; q2_=*(__half2*)&w.y; \
            w = shA[IDX(slot_, dy+3, dx)]; a3=*(__half2*)&w.x; q3_=*(__half2*)&w.y; \
            w = shA[IDX(slot_, dy+4, dx)]; a4=*(__half2*)&w.x; q4_=*(__half2*)&w.y; \
            w = shA[IDX(slot_, dy+5, dx)]; a5=*(__half2*)&w.x; q5_=*(__half2*)&w.y; \
            e0 = __half2float(shE[IDX(slot_, dy+0, dx)]);                         \
            e1 = __half2float(shE[IDX(slot_, dy+1, dx)]);                         \
            e2 = __half2float(shE[IDX(slot_, dy+2, dx)]);                         \
            e3 = __half2float(shE[IDX(slot_, dy+3, dx)]);                         \
            e4 = __half2float(shE[IDX(slot_, dy+4, dx)]);                         \
            e5 = __half2float(shE[IDX(slot_, dy+5, dx)]);                         \
        }                                                                         \
        const __half2 yA0 = __hadd2(__hadd2(__hadd2(a0,a1), __hadd2(a2,a3)), a4); \
        const __half2 yA1 = __hadd2(__hsub2(yA0, a0), a5);                        \
        const __half2 yQ0 = __hadd2(__hadd2(__hadd2(q0_,q1_), __hadd2(q2_,q3_)), q4_); \
        const __half2 yQ1 = __hadd2(__hsub2(yQ0, q0_), q5_);                      \
        const float   yE0 = ((e0 + e1) + (e2 + e3)) + e4;                         \
        const float   yE1 = yE0 - e0 + e5;                                        \
        ringA[0][SLOT] = yA0;  ringA[1][SLOT] = yA1;                              \
        ringQ[0][SLOT] = yQ0;  ringQ[1][SLOT] = yQ1;                              \
        ringE[0][SLOT] = yE0;  ringE[1][SLOT] = yE1;                              \
        if ((IT) >= 4) {                                                          \
            const float INV = 1.0f / 125.0f;                                      \
            _Pragma("unroll")                                                     \
            for (int o = 0; o < 2; ++o) {                                         \
                const __half2 SA = __hadd2(__hadd2(__hadd2(ringA[o][0], ringA[o][1]), \
                                   __hadd2(ringA[o][2], ringA[o][3])), ringA[o][4]); \
                const __half2 SQ = __hadd2(__hadd2(__hadd2(ringQ[o][0], ringQ[o][1]), \
                                   __hadd2(ringQ[o][2], ringQ[o][3])), ringQ[o][4]); \
                const float SE = ((ringE[o][0] + ringE[o][1]) +                   \
                                  (ringE[o][2] + ringE[o][3])) + ringE[o][4];     \
                const float2 sa = __half22float2(SA);                             \
                const float2 sq = __half22float2(SQ);                             \
                const float uI = sa.x * INV, uJ = sa.y * INV;                     \
                const float cross = fmaf(-uI, uJ, SE * INV);                      \
                const float vi    = fmaf(-uI, uI, sq.x * INV);                    \
                const float vj    = fmaf(-uJ, uJ, sq.y * INV);                    \
                acc += __fdividef(cross * cross, fmaf(vi, vj, 1e-5f));            \
            }                                                                     \
        }                                                                         \
    } while (0)

    // preload pair 0 (planes z0-2, z0-1)
    if (bAct) { LOADP(0, z0 - 2); LOADP(1, z0 - 1); }

    for (int g = 0; g < PAIRS / 5; ++g) {          // 10 groups of 5 pairs
#pragma unroll
        for (int j = 0; j < 5; ++j) {
            const int pi = g * 5 + j;              // pair index 0..49
            const int pb = (g + j) & 1;
            const int it0 = 2 * pi;                // first plane index of pair

            if (bAct) {
                BST(0, pb);
                BST(1, pb);
                if (pi < PAIRS - 1) {              // prefetch next pair
                    LOADP(0, z0 + 2 * pi);
                    LOADP(1, z0 + 2 * pi + 1);
                }
            }
            __syncthreads();

            DST(pb, 0, (2 * j) % 5,     it0);
            DST(pb, 1, (2 * j + 1) % 5, it0 + 1);
        }
    }

#undef LOADP
#undef BST
#undef DST

    // ---- Reduction ----
#pragma unroll
    for (int o = 16; o > 0; o >>= 1)
        acc += __shfl_xor_sync(0xffffffffu, acc, o);
    if ((tid & 31) == 0)
        atomicAdd(&blockAcc, acc);
    __syncthreads();
    if (tid == 0) {
        const float INVN = 1.0f / (float)((long)NB * DSZ * DSZ * DSZ);
        atomicAdd(out, -blockAcc * INVN);
    }
}

extern "C" void kernel_launch(void* const* d_in, const int* in_sizes, int n_in,
                              void* d_out, int out_size)
{
    const float* pred = (const float*)d_in[0];
    const float* targ = (const float*)d_in[1];
    float* out = (float*)d_out;

    cudaFuncSetAttribute(lncc_kernel,
                         cudaFuncAttributeMaxDynamicSharedMemorySize, SMEM_BYTES);

    hx_zero_out<<<1, 1>>>(out);

    dim3 grid(DSZ / TX, DSZ / TY, NB * (DSZ / ZCH));   // 6 x 12 x 4 = 288 blocks
    lncc_kernel<<<grid, NT, SMEM_BYTES>>>(pred, targ, out);
}

// round 10
// speedup vs baseline: 2.6145x; 1.0095x over previous
#include <cuda_runtime.h>
#include <cuda_fp16.h>

#define DSZ 192
#define PL  (DSZ * DSZ)
#define NB  2
#define TX  32                   // tile width (x)
#define TY  8                    // tile height (y)
#define ZCH 96                   // z outputs per block
#define NT  128
#define HR  12                   // TY + 4
#define PAIRS 50                 // 100 planes per block, 2 per iteration

// element index within one [slot][row][x] array (4 slots = 2 pairbufs x 2 planes)
#define IDX(slot,rw,x) (((slot)*HR + (rw))*TX + (x))
#define NELT (4*HR*TX)
// shA: uint2 {half2(I,J), half2(I2,J2)} | shE: half (IJ)
#define SMEM_BYTES (NELT*8 + NELT*2)

__global__ void hx_zero_out(float* out) { out[0] = 0.0f; }

__global__ __launch_bounds__(NT, 4)
void lncc_kernel(const float* __restrict__ pred,
                 const float* __restrict__ targ,
                 float* __restrict__ out)
{
    extern __shared__ char shm[];
    uint2*  const shA = (uint2*)shm;                 // (I,J | I2,J2) packed halves
    __half* const shE = (__half*)(shA + NELT);       // IJ
    __shared__ float blockAcc;

    const int tid = threadIdx.x;
    const int bx = blockIdx.x, by = blockIdx.y;
    const int batch = blockIdx.z >> 1;
    const int z0    = (blockIdx.z & 1) * ZCH;

    if (tid == 0) blockAcc = 0.0f;

    // ---- Stage B mapping: 96 active threads = 12 rows x 8 x-chunks of 4 ----
    const int  r    = tid >> 3;                 // 0..15 (active < 12)
    const int  xq   = tid & 7;
    const bool bAct = (r < HR);
    const int  gy   = by * TY + r - 2;
    const bool rowok = bAct && ((unsigned)gy < (unsigned)DSZ);
    const int  gx0  = bx * TX + 4 * xq - 2;
    const bool c0 = rowok && ((unsigned)(gx0    ) <= 190u);
    const bool c1 = rowok && ((unsigned)(gx0 + 2) <= 190u);
    const bool c2 = rowok && ((unsigned)(gx0 + 4) <= 190u);
    const bool c3 = rowok && ((unsigned)(gx0 + 6) <= 190u);

    const int gyc = gy < 0 ? 0 : (gy > DSZ - 1 ? DSZ - 1 : gy);
    const long off = (long)batch * DSZ * PL + (long)gyc * DSZ + gx0;
    const float* pB = pred + off;
    const float* tB = targ + off;

    // ---- Stage D mapping: each thread owns 2 adjacent y outputs ----
    const int dy = (tid >> 5) * 2;              // 0,2,4,6
    const int dx = tid & 31;

    float2 Lp[2][4], Lt[2][4];       // prefetched inputs for a plane pair
    const float2 Z2 = make_float2(0.f, 0.f);

#define LOADP(PLN, ZI) do {                                               \
        const int  zi_  = (ZI);                                           \
        const bool zok_ = (unsigned)zi_ < (unsigned)DSZ;                  \
        const long po_  = (long)(zok_ ? zi_ : 0) * PL;                    \
        Lp[PLN][0] = (zok_ && c0) ? *(const float2*)(pB + po_    ) : Z2;  \
        Lp[PLN][1] = (zok_ && c1) ? *(const float2*)(pB + po_ + 2) : Z2;  \
        Lp[PLN][2] = (zok_ && c2) ? *(const float2*)(pB + po_ + 4) : Z2;  \
        Lp[PLN][3] = (zok_ && c3) ? *(const float2*)(pB + po_ + 6) : Z2;  \
        Lt[PLN][0] = (zok_ && c0) ? *(const float2*)(tB + po_    ) : Z2;  \
        Lt[PLN][1] = (zok_ && c1) ? *(const float2*)(tB + po_ + 2) : Z2;  \
        Lt[PLN][2] = (zok_ && c2) ? *(const float2*)(tB + po_ + 4) : Z2;  \
        Lt[PLN][3] = (zok_ && c3) ? *(const float2*)(tB + po_ + 6) : Z2;  \
    } while (0)

#define BST(PLN, PB) do {                                                          \
        const float p0=Lp[PLN][0].x,p1=Lp[PLN][0].y,p2=Lp[PLN][1].x,p3=Lp[PLN][1].y; \
        const float p4=Lp[PLN][2].x,p5=Lp[PLN][2].y,p6=Lp[PLN][3].x,p7=Lp[PLN][3].y; \
        const float q0=Lt[PLN][0].x,q1=Lt[PLN][0].y,q2=Lt[PLN][1].x,q3=Lt[PLN][1].y; \
        const float q4=Lt[PLN][2].x,q5=Lt[PLN][2].y,q6=Lt[PLN][3].x,q7=Lt[PLN][3].y; \
        float4 oI, oJ, oII, oJJ, oIJ;                                              \
        oI.x = p0 + p1 + p2 + p3 + p4;                                             \
        oI.y = oI.x - p0 + p5;  oI.z = oI.y - p1 + p6;  oI.w = oI.z - p2 + p7;     \
        oJ.x = q0 + q1 + q2 + q3 + q4;                                             \
        oJ.y = oJ.x - q0 + q5;  oJ.z = oJ.y - q1 + q6;  oJ.w = oJ.z - q2 + q7;     \
        oII.x = fmaf(p4,p4, fmaf(p3,p3, fmaf(p2,p2, fmaf(p1,p1, p0*p0))));         \
        oII.y = fmaf(p5,p5, fmaf(-p0,p0, oII.x));                                  \
        oII.z = fmaf(p6,p6, fmaf(-p1,p1, oII.y));                                  \
        oII.w = fmaf(p7,p7, fmaf(-p2,p2, oII.z));                                  \
        oJJ.x = fmaf(q4,q4, fmaf(q3,q3, fmaf(q2,q2, fmaf(q1,q1, q0*q0))));         \
        oJJ.y = fmaf(q5,q5, fmaf(-q0,q0, oJJ.x));                                  \
        oJJ.z = fmaf(q6,q6, fmaf(-q1,q1, oJJ.y));                                  \
        oJJ.w = fmaf(q7,q7, fmaf(-q2,q2, oJJ.z));                                  \
        oIJ.x = fmaf(p4,q4, fmaf(p3,q3, fmaf(p2,q2, fmaf(p1,q1, p0*q0))));         \
        oIJ.y = fmaf(p5,q5, fmaf(-p0,q0, oIJ.x));                                  \
        oIJ.z = fmaf(p6,q6, fmaf(-p1,q1, oIJ.y));                                  \
        oIJ.w = fmaf(p7,q7, fmaf(-p2,q2, oIJ.z));                                  \
        const int slot_ = (PB)*2 + (PLN);                                          \
        __half2 t_;                                                               \
        uint4 u0, u1; uint2 uE;                                                    \
        t_ = __floats2half2_rn(oI.x,  oJ.x ); u0.x = *(unsigned*)&t_;              \
        t_ = __floats2half2_rn(oII.x, oJJ.x); u0.y = *(unsigned*)&t_;              \
        t_ = __floats2half2_rn(oI.y,  oJ.y ); u0.z = *(unsigned*)&t_;              \
        t_ = __floats2half2_rn(oII.y, oJJ.y); u0.w = *(unsigned*)&t_;              \
        t_ = __floats2half2_rn(oI.z,  oJ.z ); u1.x = *(unsigned*)&t_;              \
        t_ = __floats2half2_rn(oII.z, oJJ.z); u1.y = *(unsigned*)&t_;              \
        t_ = __floats2half2_rn(oI.w,  oJ.w ); u1.z = *(unsigned*)&t_;              \
        t_ = __floats2half2_rn(oII.w, oJJ.w); u1.w = *(unsigned*)&t_;              \
        t_ = __floats2half2_rn(oIJ.x, oIJ.y); uE.x = *(unsigned*)&t_;              \
        t_ = __floats2half2_rn(oIJ.z, oIJ.w); uE.y = *(unsigned*)&t_;              \
        *(uint4*)&shA[IDX(slot_, r, 4*xq)    ] = u0;                               \
        *(uint4*)&shA[IDX(slot_, r, 4*xq) + 2] = u1;                               \
        *(uint2*)&shE[IDX(slot_, r, 4*xq)]     = uE;                               \
    } while (0)

    // z ring: half2 y-sums for (I,J) and (I2,J2), fp32 for IJ
    __half2 ringA[2][5], ringQ[2][5];
    float   ringE[2][5];
    const __half2 HZ = __floats2half2_rn(0.f, 0.f);
#pragma unroll
    for (int o = 0; o < 2; ++o)
#pragma unroll
        for (int s = 0; s < 5; ++s) { ringA[o][s] = HZ; ringQ[o][s] = HZ; ringE[o][s] = 0.f; }
    float acc = 0.f;

    // D stage for one plane: SIMD y-sums + fresh 5-slot z-sums
#define DST(PB, PLN, SLOT, IT) do {                                               \
        const int slot_ = (PB)*2 + (PLN);                                         \
        __half2 a0,a1,a2,a3,a4,a5, q0_,q1_,q2_,q3_,q4_,q5_;                       \
        float e0,e1,e2,e3,e4,e5;                                                  \
        {                                                                         \
            uint2 w;                                                              \
            w = shA[IDX(slot_, dy+0, dx)]; a0=*(__half2*)&w.x; q0_=*(__half2*)&w.y; \
            w = shA[IDX(slot_, dy+1, dx)]; a1=*(__half2*)&w.x; q1_=*(__half2*)&w.y; \
            w = shA[IDX(slot_, dy+2, dx)]; a2=*(__half2*)&w.x; q2_=*(__half2*)&w.y; \
            w = shA[IDX(slot_, dy+3, dx)]; a3=*(__half2*)&w.x; q3_=*(__half2*)&w.y; \
            w = shA[IDX(slot_, dy+4, dx)]; a4=*(__half2*)&w.x; q4_=*(__half2*)&w.y; \
            w = shA[IDX(slot_, dy+5, dx)]; a5=*(__half2*)&w.x; q5_=*(__half2*)&w.y; \
            e0 = __half2float(shE[IDX(slot_, dy+0, dx)]);                         \
            e1 = __half2float(shE[IDX(slot_, dy+1, dx)]);                         \
            e2 = __half2float(shE[IDX(slot_, dy+2, dx)]);                         \
            e3 = __half2float(shE[IDX(slot_, dy+3, dx)]);                         \
            e4 = __half2float(shE[IDX(slot_, dy+4, dx)]);                         \
            e5 = __half2float(shE[IDX(slot_, dy+5, dx)]);                         \
        }                                                                         \
        const __half2 yA0 = __hadd2(__hadd2(__hadd2(a0,a1), __hadd2(a2,a3)), a4); \
        const __half2 yA1 = __hadd2(__hsub2(yA0, a0), a5);                        \
        const __half2 yQ0 = __hadd2(__hadd2(__hadd2(q0_,q1_), __hadd2(q2_,q3_)), q4_); \
        const __half2 yQ1 = __hadd2(__hsub2(yQ0, q0_), q5_);                      \
        const float   yE0 = ((e0 + e1) + (e2 + e3)) + e4;                         \
        const float   yE1 = yE0 - e0 + e5;                                        \
        ringA[0][SLOT] = yA0;  ringA[1][SLOT] = yA1;                              \
        ringQ[0][SLOT] = yQ0;  ringQ[1][SLOT] = yQ1;                              \
        ringE[0][SLOT] = yE0;  ringE[1][SLOT] = yE1;                              \
        if ((IT) >= 4) {                                                          \
            const float INV = 1.0f / 125.0f;                                      \
            _Pragma("unroll")                                                     \
            for (int o = 0; o < 2; ++o) {                                         \
                const __half2 SA = __hadd2(__hadd2(__hadd2(ringA[o][0], ringA[o][1]), \
                                   __hadd2(ringA[o][2], ringA[o][3])), ringA[o][4]); \
                const __half2 SQ = __hadd2(__hadd2(__hadd2(ringQ[o][0], ringQ[o][1]), \
                                   __hadd2(ringQ[o][2], ringQ[o][3])), ringQ[o][4]); \
                const float SE = ((ringE[o][0] + ringE[o][1]) +                   \
                                  (ringE[o][2] + ringE[o][3])) + ringE[o][4];     \
                const float2 sa = __half22float2(SA);                             \
                const float2 sq = __half22float2(SQ);                             \
                const float uI = sa.x * INV, uJ = sa.y * INV;                     \
                const float cross = fmaf(-uI, uJ, SE * INV);                      \
                const float vi    = fmaf(-uI, uI, sq.x * INV);                    \
                const float vj    = fmaf(-uJ, uJ, sq.y * INV);                    \
                acc += __fdividef(cross * cross, fmaf(vi, vj, 1e-5f));            \
            }                                                                     \
        }                                                                         \
    } while (0)

    // preload pair 0 (planes z0-2, z0-1)
    if (bAct) { LOADP(0, z0 - 2); LOADP(1, z0 - 1); }

    for (int g = 0; g < PAIRS / 5; ++g) {          // 10 groups of 5 pairs
#pragma unroll
        for (int j = 0; j < 5; ++j) {
            const int pi = g * 5 + j;              // pair index 0..49
            const int pb = (g + j) & 1;
            const int it0 = 2 * pi;                // first plane index of pair

            if (bAct) {
                BST(0, pb);
                BST(1, pb);
                if (pi < PAIRS - 1) {              // prefetch next pair
                    LOADP(0, z0 + 2 * pi);
                    LOADP(1, z0 + 2 * pi + 1);
                }
            }
            __syncthreads();

            DST(pb, 0, (2 * j) % 5,     it0);
            DST(pb, 1, (2 * j + 1) % 5, it0 + 1);
        }
    }

#undef LOADP
#undef BST
#undef DST

    // ---- Reduction ----
#pragma unroll
    for (int o = 16; o > 0; o >>= 1)
        acc += __shfl_xor_sync(0xffffffffu, acc, o);
    if ((tid & 31) == 0)
        atomicAdd(&blockAcc, acc);
    __syncthreads();
    if (tid == 0) {
        const float INVN = 1.0f / (float)((long)NB * DSZ * DSZ * DSZ);
        atomicAdd(out, -blockAcc * INVN);
    }
}

extern "C" void kernel_launch(void* const* d_in, const int* in_sizes, int n_in,
                              void* d_out, int out_size)
{
    const float* pred = (const float*)d_in[0];
    const float* targ = (const float*)d_in[1];
    float* out = (float*)d_out;

    cudaFuncSetAttribute(lncc_kernel,
                         cudaFuncAttributeMaxDynamicSharedMemorySize, SMEM_BYTES);

    hx_zero_out<<<1, 1>>>(out);

    dim3 grid(DSZ / TX, DSZ / TY, NB * (DSZ / ZCH));   // 6 x 24 x 4 = 576 blocks
    lncc_kernel<<<grid, NT, SMEM_BYTES>>>(pred, targ, out);
}

// round 11
// speedup vs baseline: 2.6535x; 1.0149x over previous
#include <cuda_runtime.h>
#include <cuda_fp16.h>

#define DSZ 192
#define PL  (DSZ * DSZ)
#define NB  2
#define TX  32                   // tile width (x)
#define TY  12                   // tile height (y)
#define ZCH 64                   // z outputs per block (3 chunks cover 192)
#define NT  128
#define HR  16                   // TY + 4  -> 16 rows x 8 chunks = 128 threads exactly
#define PAIRS 35                 // 70 planes processed (68 needed + 2 pad, gated)

// element index within one [slot][row][x] array (4 slots = 2 pairbufs x 2 planes)
#define IDX(slot,rw,x) (((slot)*HR + (rw))*TX + (x))
#define NELT (4*HR*TX)
// shA: uint2 {half2(I,J), half2(I2,J2)} | shE: half (IJ)
#define SMEM_BYTES (NELT*8 + NELT*2)

__global__ void hx_zero_out(float* out) { out[0] = 0.0f; }

__global__ __launch_bounds__(NT, 4)
void lncc_kernel(const float* __restrict__ pred,
                 const float* __restrict__ targ,
                 float* __restrict__ out)
{
    extern __shared__ char shm[];
    uint2*  const shA = (uint2*)shm;                 // (I,J | I2,J2) packed halves
    __half* const shE = (__half*)(shA + NELT);       // IJ
    __shared__ float blockAcc;

    const int tid = threadIdx.x;
    const int bx = blockIdx.x, by = blockIdx.y;
    const int batch = blockIdx.z / 3;
    const int z0    = (blockIdx.z % 3) * ZCH;

    if (tid == 0) blockAcc = 0.0f;

    // ---- Stage B mapping: ALL 128 threads = 16 rows x 8 x-chunks of 4 ----
    const int  r    = tid >> 3;                 // 0..15
    const int  xq   = tid & 7;
    const int  gy   = by * TY + r - 2;
    const bool rowok = (unsigned)gy < (unsigned)DSZ;
    const int  gx0  = bx * TX + 4 * xq - 2;
    const bool c0 = rowok && ((unsigned)(gx0    ) <= 190u);
    const bool c1 = rowok && ((unsigned)(gx0 + 2) <= 190u);
    const bool c2 = rowok && ((unsigned)(gx0 + 4) <= 190u);
    const bool c3 = rowok && ((unsigned)(gx0 + 6) <= 190u);

    const int gyc = gy < 0 ? 0 : (gy > DSZ - 1 ? DSZ - 1 : gy);
    const long off = (long)batch * DSZ * PL + (long)gyc * DSZ + gx0;
    const float* pB = pred + off;
    const float* tB = targ + off;

    // ---- Stage D mapping: each thread owns 3 adjacent y outputs ----
    const int dy = (tid >> 5) * 3;              // 0,3,6,9
    const int dx = tid & 31;

    float2 Lp[2][4], Lt[2][4];       // prefetched inputs for a plane pair
    const float2 Z2 = make_float2(0.f, 0.f);

#define LOADP(PLN, ZI) do {                                               \
        const int  zi_  = (ZI);                                           \
        const bool zok_ = (unsigned)zi_ < (unsigned)DSZ;                  \
        const long po_  = (long)(zok_ ? zi_ : 0) * PL;                    \
        Lp[PLN][0] = (zok_ && c0) ? *(const float2*)(pB + po_    ) : Z2;  \
        Lp[PLN][1] = (zok_ && c1) ? *(const float2*)(pB + po_ + 2) : Z2;  \
        Lp[PLN][2] = (zok_ && c2) ? *(const float2*)(pB + po_ + 4) : Z2;  \
        Lp[PLN][3] = (zok_ && c3) ? *(const float2*)(pB + po_ + 6) : Z2;  \
        Lt[PLN][0] = (zok_ && c0) ? *(const float2*)(tB + po_    ) : Z2;  \
        Lt[PLN][1] = (zok_ && c1) ? *(const float2*)(tB + po_ + 2) : Z2;  \
        Lt[PLN][2] = (zok_ && c2) ? *(const float2*)(tB + po_ + 4) : Z2;  \
        Lt[PLN][3] = (zok_ && c3) ? *(const float2*)(tB + po_ + 6) : Z2;  \
    } while (0)

#define BST(PLN, PB) do {                                                          \
        const float p0=Lp[PLN][0].x,p1=Lp[PLN][0].y,p2=Lp[PLN][1].x,p3=Lp[PLN][1].y; \
        const float p4=Lp[PLN][2].x,p5=Lp[PLN][2].y,p6=Lp[PLN][3].x,p7=Lp[PLN][3].y; \
        const float q0=Lt[PLN][0].x,q1=Lt[PLN][0].y,q2=Lt[PLN][1].x,q3=Lt[PLN][1].y; \
        const float q4=Lt[PLN][2].x,q5=Lt[PLN][2].y,q6=Lt[PLN][3].x,q7=Lt[PLN][3].y; \
        float4 oI, oJ, oII, oJJ, oIJ;                                              \
        oI.x = p0 + p1 + p2 + p3 + p4;                                             \
        oI.y = oI.x - p0 + p5;  oI.z = oI.y - p1 + p6;  oI.w = oI.z - p2 + p7;     \
        oJ.x = q0 + q1 + q2 + q3 + q4;                                             \
        oJ.y = oJ.x - q0 + q5;  oJ.z = oJ.y - q1 + q6;  oJ.w = oJ.z - q2 + q7;     \
        oII.x = fmaf(p4,p4, fmaf(p3,p3, fmaf(p2,p2, fmaf(p1,p1, p0*p0))));         \
        oII.y = fmaf(p5,p5, fmaf(-p0,p0, oII.x));                                  \
        oII.z = fmaf(p6,p6, fmaf(-p1,p1, oII.y));                                  \
        oII.w = fmaf(p7,p7, fmaf(-p2,p2, oII.z));                                  \
        oJJ.x = fmaf(q4,q4, fmaf(q3,q3, fmaf(q2,q2, fmaf(q1,q1, q0*q0))));         \
        oJJ.y = fmaf(q5,q5, fmaf(-q0,q0, oJJ.x));                                  \
        oJJ.z = fmaf(q6,q6, fmaf(-q1,q1, oJJ.y));                                  \
        oJJ.w = fmaf(q7,q7, fmaf(-q2,q2, oJJ.z));                                  \
        oIJ.x = fmaf(p4,q4, fmaf(p3,q3, fmaf(p2,q2, fmaf(p1,q1, p0*q0))));         \
        oIJ.y = fmaf(p5,q5, fmaf(-p0,q0, oIJ.x));                                  \
        oIJ.z = fmaf(p6,q6, fmaf(-p1,q1, oIJ.y));                                  \
        oIJ.w = fmaf(p7,q7, fmaf(-p2,q2, oIJ.z));                                  \
        const int slot_ = (PB)*2 + (PLN);                                          \
        __half2 t_;                                                               \
        uint4 u0, u1; uint2 uE;                                                    \
        t_ = __floats2half2_rn(oI.x,  oJ.x ); u0.x = *(unsigned*)&t_;              \
        t_ = __floats2half2_rn(oII.x, oJJ.x); u0.y = *(unsigned*)&t_;              \
        t_ = __floats2half2_rn(oI.y,  oJ.y ); u0.z = *(unsigned*)&t_;              \
        t_ = __floats2half2_rn(oII.y, oJJ.y); u0.w = *(unsigned*)&t_;              \
        t_ = __floats2half2_rn(oI.z,  oJ.z ); u1.x = *(unsigned*)&t_;              \
        t_ = __floats2half2_rn(oII.z, oJJ.z); u1.y = *(unsigned*)&t_;              \
        t_ = __floats2half2_rn(oI.w,  oJ.w ); u1.z = *(unsigned*)&t_;              \
        t_ = __floats2half2_rn(oII.w, oJJ.w); u1.w = *(unsigned*)&t_;              \
        t_ = __floats2half2_rn(oIJ.x, oIJ.y); uE.x = *(unsigned*)&t_;              \
        t_ = __floats2half2_rn(oIJ.z, oIJ.w); uE.y = *(unsigned*)&t_;              \
        *(uint4*)&shA[IDX(slot_, r, 4*xq)    ] = u0;                               \
        *(uint4*)&shA[IDX(slot_, r, 4*xq) + 2] = u1;                               \
        *(uint2*)&shE[IDX(slot_, r, 4*xq)]     = uE;                               \
    } while (0)

    // z ring: half2 y-sums for (I,J) and (I2,J2), fp32 for IJ — 3 y-outputs
    __half2 ringA[3][5], ringQ[3][5];
    float   ringE[3][5];
    const __half2 HZ = __floats2half2_rn(0.f, 0.f);
#pragma unroll
    for (int o = 0; o < 3; ++o)
#pragma unroll
        for (int s = 0; s < 5; ++s) { ringA[o][s] = HZ; ringQ[o][s] = HZ; ringE[o][s] = 0.f; }
    float acc = 0.f;

    // D stage for one plane: SIMD sliding y-sums over 7 rows -> 3 outputs
#define DST(PB, PLN, SLOT, IT) do {                                               \
        const int slot_ = (PB)*2 + (PLN);                                         \
        __half2 a0,a1,a2,a3,a4,a5,a6, q0_,q1_,q2_,q3_,q4_,q5_,q6_;                \
        float e0,e1,e2,e3,e4,e5,e6;                                               \
        {                                                                         \
            uint2 w;                                                              \
            w = shA[IDX(slot_, dy+0, dx)]; a0=*(__half2*)&w.x; q0_=*(__half2*)&w.y; \
            w = shA[IDX(slot_, dy+1, dx)]; a1=*(__half2*)&w.x; q1_=*(__half2*)&w.y; \
            w = shA[IDX(slot_, dy+2, dx)]; a2=*(__half2*)&w.x; q2_=*(__half2*)&w.y; \
            w = shA[IDX(slot_, dy+3, dx)]; a3=*(__half2*)&w.x; q3_=*(__half2*)&w.y; \
            w = shA[IDX(slot_, dy+4, dx)]; a4=*(__half2*)&w.x; q4_=*(__half2*)&w.y; \
            w = shA[IDX(slot_, dy+5, dx)]; a5=*(__half2*)&w.x; q5_=*(__half2*)&w.y; \
            w = shA[IDX(slot_, dy+6, dx)]; a6=*(__half2*)&w.x; q6_=*(__half2*)&w.y; \
            e0 = __half2float(shE[IDX(slot_, dy+0, dx)]);                         \
            e1 = __half2float(shE[IDX(slot_, dy+1, dx)]);                         \
            e2 = __half2float(shE[IDX(slot_, dy+2, dx)]);                         \
            e3 = __half2float(shE[IDX(slot_, dy+3, dx)]);                         \
            e4 = __half2float(shE[IDX(slot_, dy+4, dx)]);                         \
            e5 = __half2float(shE[IDX(slot_, dy+5, dx)]);                         \
            e6 = __half2float(shE[IDX(slot_, dy+6, dx)]);                         \
        }                                                                         \
        const __half2 yA0 = __hadd2(__hadd2(__hadd2(a0,a1), __hadd2(a2,a3)), a4); \
        const __half2 yA1 = __hadd2(__hsub2(yA0, a0), a5);                        \
        const __half2 yA2 = __hadd2(__hsub2(yA1, a1), a6);                        \
        const __half2 yQ0 = __hadd2(__hadd2(__hadd2(q0_,q1_), __hadd2(q2_,q3_)), q4_); \
        const __half2 yQ1 = __hadd2(__hsub2(yQ0, q0_), q5_);                      \
        const __half2 yQ2 = __hadd2(__hsub2(yQ1, q1_), q6_);                      \
        const float   yE0 = ((e0 + e1) + (e2 + e3)) + e4;                         \
        const float   yE1 = yE0 - e0 + e5;                                        \
        const float   yE2 = yE1 - e1 + e6;                                        \
        ringA[0][SLOT] = yA0;  ringA[1][SLOT] = yA1;  ringA[2][SLOT] = yA2;       \
        ringQ[0][SLOT] = yQ0;  ringQ[1][SLOT] = yQ1;  ringQ[2][SLOT] = yQ2;       \
        ringE[0][SLOT] = yE0;  ringE[1][SLOT] = yE1;  ringE[2][SLOT] = yE2;       \
        if ((IT) >= 4 && (IT) < ZCH + 4) {                                        \
            const float INV = 1.0f / 125.0f;                                      \
            _Pragma("unroll")                                                     \
            for (int o = 0; o < 3; ++o) {                                         \
                const __half2 SA = __hadd2(__hadd2(__hadd2(ringA[o][0], ringA[o][1]), \
                                   __hadd2(ringA[o][2], ringA[o][3])), ringA[o][4]); \
                const __half2 SQ = __hadd2(__hadd2(__hadd2(ringQ[o][0], ringQ[o][1]), \
                                   __hadd2(ringQ[o][2], ringQ[o][3])), ringQ[o][4]); \
                const float SE = ((ringE[o][0] + ringE[o][1]) +                   \
                                  (ringE[o][2] + ringE[o][3])) + ringE[o][4];     \
                const float2 sa = __half22float2(SA);                             \
                const float2 sq = __half22float2(SQ);                             \
                const float uI = sa.x * INV, uJ = sa.y * INV;                     \
                const float cross = fmaf(-uI, uJ, SE * INV);                      \
                const float vi    = fmaf(-uI, uI, sq.x * INV);                    \
                const float vj    = fmaf(-uJ, uJ, sq.y * INV);                    \
                acc += __fdividef(cross * cross, fmaf(vi, vj, 1e-5f));            \
            }                                                                     \
        }                                                                         \
    } while (0)

    // preload pair 0 (planes z0-2, z0-1)
    LOADP(0, z0 - 2); LOADP(1, z0 - 1);

    for (int g = 0; g < PAIRS / 5; ++g) {          // 7 groups of 5 pairs
#pragma unroll
        for (int j = 0; j < 5; ++j) {
            const int pi = g * 5 + j;              // pair index 0..34
            const int pb = (g + j) & 1;
            const int it0 = 2 * pi;                // first plane index of pair

            BST(0, pb);
            BST(1, pb);
            if (pi < PAIRS - 1) {                  // prefetch next pair
                LOADP(0, z0 + 2 * pi);
                LOADP(1, z0 + 2 * pi + 1);
            }
            __syncthreads();

            DST(pb, 0, (2 * j) % 5,     it0);
            DST(pb, 1, (2 * j + 1) % 5, it0 + 1);
        }
    }

#undef LOADP
#undef BST
#undef DST

    // ---- Reduction ----
#pragma unroll
    for (int o = 16; o > 0; o >>= 1)
        acc += __shfl_xor_sync(0xffffffffu, acc, o);
    if ((tid & 31) == 0)
        atomicAdd(&blockAcc, acc);
    __syncthreads();
    if (tid == 0) {
        const float INVN = 1.0f / (float)((long)NB * DSZ * DSZ * DSZ);
        atomicAdd(out, -blockAcc * INVN);
    }
}

extern "C" void kernel_launch(void* const* d_in, const int* in_sizes, int n_in,
                              void* d_out, int out_size)
{
    const float* pred = (const float*)d_in[0];
    const float* targ = (const float*)d_in[1];
    float* out = (float*)d_out;

    cudaFuncSetAttribute(lncc_kernel,
                         cudaFuncAttributeMaxDynamicSharedMemorySize, SMEM_BYTES);

    hx_zero_out<<<1, 1>>>(out);

    dim3 grid(DSZ / TX, DSZ / TY, NB * 3);   // 6 x 16 x 6 = 576 blocks
    lncc_kernel<<<grid, NT, SMEM_BYTES>>>(pred, targ, out);
}

// round 12
// speedup vs baseline: 2.6937x; 1.0152x over previous
#include <cuda_runtime.h>
#include <cuda_fp16.h>

#define DSZ 192
#define PL  (DSZ * DSZ)
#define NB  2
#define TX  32                   // tile width (x)
#define TY  12                   // tile height (y)
#define ZCH 64                   // z outputs per block (3 chunks cover 192)
#define NT  128
#define HR  16                   // TY + 4  -> 16 rows x 8 chunks = 128 threads exactly
#define PAIRS 35                 // 70 planes processed (68 needed + 2 pad, gated)
#define NBLOCKS (6 * 16 * 6)     // grid size = 576

// element index within one [slot][row][x] array (4 slots = 2 pairbufs x 2 planes)
#define IDX(slot,rw,x) (((slot)*HR + (rw))*TX + (x))
#define NELT (4*HR*TX)
// shA: uint2 {half2(I,J), half2(I2,J2)} | shE: half (IJ)
#define SMEM_BYTES (NELT*8 + NELT*2)

// Cross-block reduction state. Initially zero; the LAST block of every launch
// resets both to zero again, so each graph replay starts from the same state.
__device__ float    g_sum    = 0.0f;
__device__ unsigned g_ticket = 0u;

__global__ __launch_bounds__(NT, 4)
void lncc_kernel(const float* __restrict__ pred,
                 const float* __restrict__ targ,
                 float* __restrict__ out)
{
    extern __shared__ char shm[];
    uint2*  const shA = (uint2*)shm;                 // (I,J | I2,J2) packed halves
    __half* const shE = (__half*)(shA + NELT);       // IJ
    __shared__ float blockAcc;

    const int tid = threadIdx.x;
    const int bx = blockIdx.x, by = blockIdx.y;
    const int batch = blockIdx.z / 3;
    const int z0    = (blockIdx.z % 3) * ZCH;

    if (tid == 0) blockAcc = 0.0f;

    // ---- Stage B mapping: ALL 128 threads = 16 rows x 8 x-chunks of 4 ----
    const int  r    = tid >> 3;                 // 0..15
    const int  xq   = tid & 7;
    const int  gy   = by * TY + r - 2;
    const bool rowok = (unsigned)gy < (unsigned)DSZ;
    const int  gx0  = bx * TX + 4 * xq - 2;
    const bool c0 = rowok && ((unsigned)(gx0    ) <= 190u);
    const bool c1 = rowok && ((unsigned)(gx0 + 2) <= 190u);
    const bool c2 = rowok && ((unsigned)(gx0 + 4) <= 190u);
    const bool c3 = rowok && ((unsigned)(gx0 + 6) <= 190u);

    const int gyc = gy < 0 ? 0 : (gy > DSZ - 1 ? DSZ - 1 : gy);
    const long off = (long)batch * DSZ * PL + (long)gyc * DSZ + gx0;
    const float* pB = pred + off;
    const float* tB = targ + off;

    // ---- Stage D mapping: each thread owns 3 adjacent y outputs ----
    const int dy = (tid >> 5) * 3;              // 0,3,6,9
    const int dx = tid & 31;

    float2 Lp[2][4], Lt[2][4];       // prefetched inputs for a plane pair
    const float2 Z2 = make_float2(0.f, 0.f);

#define LOADP(PLN, ZI) do {                                               \
        const int  zi_  = (ZI);                                           \
        const bool zok_ = (unsigned)zi_ < (unsigned)DSZ;                  \
        const long po_  = (long)(zok_ ? zi_ : 0) * PL;                    \
        Lp[PLN][0] = (zok_ && c0) ? *(const float2*)(pB + po_    ) : Z2;  \
        Lp[PLN][1] = (zok_ && c1) ? *(const float2*)(pB + po_ + 2) : Z2;  \
        Lp[PLN][2] = (zok_ && c2) ? *(const float2*)(pB + po_ + 4) : Z2;  \
        Lp[PLN][3] = (zok_ && c3) ? *(const float2*)(pB + po_ + 6) : Z2;  \
        Lt[PLN][0] = (zok_ && c0) ? *(const float2*)(tB + po_    ) : Z2;  \
        Lt[PLN][1] = (zok_ && c1) ? *(const float2*)(tB + po_ + 2) : Z2;  \
        Lt[PLN][2] = (zok_ && c2) ? *(const float2*)(tB + po_ + 4) : Z2;  \
        Lt[PLN][3] = (zok_ && c3) ? *(const float2*)(tB + po_ + 6) : Z2;  \
    } while (0)

#define BST(PLN, PB) do {                                                          \
        const float p0=Lp[PLN][0].x,p1=Lp[PLN][0].y,p2=Lp[PLN][1].x,p3=Lp[PLN][1].y; \
        const float p4=Lp[PLN][2].x,p5=Lp[PLN][2].y,p6=Lp[PLN][3].x,p7=Lp[PLN][3].y; \
        const float q0=Lt[PLN][0].x,q1=Lt[PLN][0].y,q2=Lt[PLN][1].x,q3=Lt[PLN][1].y; \
        const float q4=Lt[PLN][2].x,q5=Lt[PLN][2].y,q6=Lt[PLN][3].x,q7=Lt[PLN][3].y; \
        float4 oI, oJ, oII, oJJ, oIJ;                                              \
        oI.x = p0 + p1 + p2 + p3 + p4;                                             \
        oI.y = oI.x - p0 + p5;  oI.z = oI.y - p1 + p6;  oI.w = oI.z - p2 + p7;     \
        oJ.x = q0 + q1 + q2 + q3 + q4;                                             \
        oJ.y = oJ.x - q0 + q5;  oJ.z = oJ.y - q1 + q6;  oJ.w = oJ.z - q2 + q7;     \
        oII.x = fmaf(p4,p4, fmaf(p3,p3, fmaf(p2,p2, fmaf(p1,p1, p0*p0))));         \
        oII.y = fmaf(p5,p5, fmaf(-p0,p0, oII.x));                                  \
        oII.z = fmaf(p6,p6, fmaf(-p1,p1, oII.y));                                  \
        oII.w = fmaf(p7,p7, fmaf(-p2,p2, oII.z));                                  \
        oJJ.x = fmaf(q4,q4, fmaf(q3,q3, fmaf(q2,q2, fmaf(q1,q1, q0*q0))));         \
        oJJ.y = fmaf(q5,q5, fmaf(-q0,q0, oJJ.x));                                  \
        oJJ.z = fmaf(q6,q6, fmaf(-q1,q1, oJJ.y));                                  \
        oJJ.w = fmaf(q7,q7, fmaf(-q2,q2, oJJ.z));                                  \
        oIJ.x = fmaf(p4,q4, fmaf(p3,q3, fmaf(p2,q2, fmaf(p1,q1, p0*q0))));         \
        oIJ.y = fmaf(p5,q5, fmaf(-p0,q0, oIJ.x));                                  \
        oIJ.z = fmaf(p6,q6, fmaf(-p1,q1, oIJ.y));                                  \
        oIJ.w = fmaf(p7,q7, fmaf(-p2,q2, oIJ.z));                                  \
        const int slot_ = (PB)*2 + (PLN);                                          \
        __half2 t_;                                                               \
        uint4 u0, u1; uint2 uE;                                                    \
        t_ = __floats2half2_rn(oI.x,  oJ.x ); u0.x = *(unsigned*)&t_;              \
        t_ = __floats2half2_rn(oII.x, oJJ.x); u0.y = *(unsigned*)&t_;              \
        t_ = __floats2half2_rn(oI.y,  oJ.y ); u0.z = *(unsigned*)&t_;              \
        t_ = __floats2half2_rn(oII.y, oJJ.y); u0.w = *(unsigned*)&t_;              \
        t_ = __floats2half2_rn(oI.z,  oJ.z ); u1.x = *(unsigned*)&t_;              \
        t_ = __floats2half2_rn(oII.z, oJJ.z); u1.y = *(unsigned*)&t_;              \
        t_ = __floats2half2_rn(oI.w,  oJ.w ); u1.z = *(unsigned*)&t_;              \
        t_ = __floats2half2_rn(oII.w, oJJ.w); u1.w = *(unsigned*)&t_;              \
        t_ = __floats2half2_rn(oIJ.x, oIJ.y); uE.x = *(unsigned*)&t_;              \
        t_ = __floats2half2_rn(oIJ.z, oIJ.w); uE.y = *(unsigned*)&t_;              \
        *(uint4*)&shA[IDX(slot_, r, 4*xq)    ] = u0;                               \
        *(uint4*)&shA[IDX(slot_, r, 4*xq) + 2] = u1;                               \
        *(uint2*)&shE[IDX(slot_, r, 4*xq)]     = uE;                               \
    } while (0)

    // z ring: half2 y-sums for (I,J) and (I2,J2), fp32 for IJ — 3 y-outputs
    __half2 ringA[3][5], ringQ[3][5];
    float   ringE[3][5];
    const __half2 HZ = __floats2half2_rn(0.f, 0.f);
#pragma unroll
    for (int o = 0; o < 3; ++o)
#pragma unroll
        for (int s = 0; s < 5; ++s) { ringA[o][s] = HZ; ringQ[o][s] = HZ; ringE[o][s] = 0.f; }
    float acc = 0.f;

    // D stage for one plane: SIMD sliding y-sums over 7 rows -> 3 outputs
#define DST(PB, PLN, SLOT, IT) do {                                               \
        const int slot_ = (PB)*2 + (PLN);                                         \
        __half2 a0,a1,a2,a3,a4,a5,a6, q0_,q1_,q2_,q3_,q4_,q5_,q6_;                \
        float e0,e1,e2,e3,e4,e5,e6;                                               \
        {                                                                         \
            uint2 w;                                                              \
            w = shA[IDX(slot_, dy+0, dx)]; a0=*(__half2*)&w.x; q0_=*(__half2*)&w.y; \
            w = shA[IDX(slot_, dy+1, dx)]; a1=*(__half2*)&w.x; q1_=*(__half2*)&w.y; \
            w = shA[IDX(slot_, dy+2, dx)]; a2=*(__half2*)&w.x; q2_=*(__half2*)&w.y; \
            w = shA[IDX(slot_, dy+3, dx)]; a3=*(__half2*)&w.x; q3_=*(__half2*)&w.y; \
            w = shA[IDX(slot_, dy+4, dx)]; a4=*(__half2*)&w.x; q4_=*(__half2*)&w.y; \
            w = shA[IDX(slot_, dy+5, dx)]; a5=*(__half2*)&w.x; q5_=*(__half2*)&w.y; \
            w = shA[IDX(slot_, dy+6, dx)]; a6=*(__half2*)&w.x; q6_=*(__half2*)&w.y; \
            e0 = __half2float(shE[IDX(slot_, dy+0, dx)]);                         \
            e1 = __half2float(shE[IDX(slot_, dy+1, dx)]);                         \
            e2 = __half2float(shE[IDX(slot_, dy+2, dx)]);                         \
            e3 = __half2float(shE[IDX(slot_, dy+3, dx)]);                         \
            e4 = __half2float(shE[IDX(slot_, dy+4, dx)]);                         \
            e5 = __half2float(shE[IDX(slot_, dy+5, dx)]);                         \
            e6 = __half2float(shE[IDX(slot_, dy+6, dx)]);                         \
        }                                                                         \
        const __half2 yA0 = __hadd2(__hadd2(__hadd2(a0,a1), __hadd2(a2,a3)), a4); \
        const __half2 yA1 = __hadd2(__hsub2(yA0, a0), a5);                        \
        const __half2 yA2 = __hadd2(__hsub2(yA1, a1), a6);                        \
        const __half2 yQ0 = __hadd2(__hadd2(__hadd2(q0_,q1_), __hadd2(q2_,q3_)), q4_); \
        const __half2 yQ1 = __hadd2(__hsub2(yQ0, q0_), q5_);                      \
        const __half2 yQ2 = __hadd2(__hsub2(yQ1, q1_), q6_);                      \
        const float   yE0 = ((e0 + e1) + (e2 + e3)) + e4;                         \
        const float   yE1 = yE0 - e0 + e5;                                        \
        const float   yE2 = yE1 - e1 + e6;                                        \
        ringA[0][SLOT] = yA0;  ringA[1][SLOT] = yA1;  ringA[2][SLOT] = yA2;       \
        ringQ[0][SLOT] = yQ0;  ringQ[1][SLOT] = yQ1;  ringQ[2][SLOT] = yQ2;       \
        ringE[0][SLOT] = yE0;  ringE[1][SLOT] = yE1;  ringE[2][SLOT] = yE2;       \
        if ((IT) >= 4 && (IT) < ZCH + 4) {                                        \
            const float INV = 1.0f / 125.0f;                                      \
            _Pragma("unroll")                                                     \
            for (int o = 0; o < 3; ++o) {                                         \
                const __half2 SA = __hadd2(__hadd2(__hadd2(ringA[o][0], ringA[o][1]), \
                                   __hadd2(ringA[o][2], ringA[o][3])), ringA[o][4]); \
                const __half2 SQ = __hadd2(__hadd2(__hadd2(ringQ[o][0], ringQ[o][1]), \
                                   __hadd2(ringQ[o][2], ringQ[o][3])), ringQ[o][4]); \
                const float SE = ((ringE[o][0] + ringE[o][1]) +                   \
                                  (ringE[o][2] + ringE[o][3])) + ringE[o][4];     \
                const float2 sa = __half22float2(SA);                             \
                const float2 sq = __half22float2(SQ);                             \
                const float uI = sa.x * INV, uJ = sa.y * INV;                     \
                const float cross = fmaf(-uI, uJ, SE * INV);                      \
                const float vi    = fmaf(-uI, uI, sq.x * INV);                    \
                const float vj    = fmaf(-uJ, uJ, sq.y * INV);                    \
                acc += __fdividef(cross * cross, fmaf(vi, vj, 1e-5f));            \
            }                                                                     \
        }                                                                         \
    } while (0)

    // preload pair 0 (planes z0-2, z0-1)
    LOADP(0, z0 - 2); LOADP(1, z0 - 1);

    for (int g = 0; g < PAIRS / 5; ++g) {          // 7 groups of 5 pairs
#pragma unroll
        for (int j = 0; j < 5; ++j) {
            const int pi = g * 5 + j;              // pair index 0..34
            const int pb = (g + j) & 1;
            const int it0 = 2 * pi;                // first plane index of pair

            BST(0, pb);
            BST(1, pb);
            if (pi < PAIRS - 1) {                  // prefetch next pair
                LOADP(0, z0 + 2 * pi);
                LOADP(1, z0 + 2 * pi + 1);
            }
            __syncthreads();

            DST(pb, 0, (2 * j) % 5,     it0);
            DST(pb, 1, (2 * j + 1) % 5, it0 + 1);
        }
    }

#undef LOADP
#undef BST
#undef DST

    // ---- In-block reduction ----
#pragma unroll
    for (int o = 16; o > 0; o >>= 1)
        acc += __shfl_xor_sync(0xffffffffu, acc, o);
    if ((tid & 31) == 0)
        atomicAdd(&blockAcc, acc);
    __syncthreads();

    // ---- Cross-block reduction: last block finalizes and resets state ----
    if (tid == 0) {
        atomicAdd(&g_sum, blockAcc);
        __threadfence();                                   // publish before ticket
        const unsigned t = atomicAdd(&g_ticket, 1u);
        if (t == NBLOCKS - 1) {                            // I'm the last block
            const float s = atomicExch(&g_sum, 0.0f);      // read + reset
            const float INVN = 1.0f / (float)((long)NB * DSZ * DSZ * DSZ);
            out[0] = -s * INVN;
            __threadfence();
            g_ticket = 0u;                                 // restore initial state
        }
    }
}

extern "C" void kernel_launch(void* const* d_in, const int* in_sizes, int n_in,
                              void* d_out, int out_size)
{
    const float* pred = (const float*)d_in[0];
    const float* targ = (const float*)d_in[1];
    float* out = (float*)d_out;

    cudaFuncSetAttribute(lncc_kernel,
                         cudaFuncAttributeMaxDynamicSharedMemorySize, SMEM_BYTES);

    dim3 grid(DSZ / TX, DSZ / TY, NB * 3);   // 6 x 16 x 6 = 576 blocks
    lncc_kernel<<<grid, NT, SMEM_BYTES>>>(pred, targ, out);
}

// round 13
// speedup vs baseline: 2.8560x; 1.0602x over previous
#include <cuda_runtime.h>
#include <cuda_fp16.h>

#define DSZ 192
#define PL  (DSZ * DSZ)
#define NB  2
#define TX  32                   // tile width (x)
#define TY  12                   // tile height (y)
#define ZCH 64                   // z outputs per block (3 chunks cover 192)
#define NT  128
#define HR  16                   // TY + 4  -> 16 rows x 8 chunks = 128 threads exactly
#define PAIRS 35                 // 70 planes processed (68 needed + 2 pad, gated)
#define NBLOCKS (6 * 16 * 6)     // grid size = 576

// A-array: [slot(4 = 2 pairbufs x 2 planes)][row][x] of uint2 {half2(I,J), half2(I2,J2)}
#define IDX(slot,rw,x) (((slot)*HR + (rw))*TX + (x))
#define NELT (4*HR*TX)
// E-array: [pairbuf(2)][row][x] of half2 (IJ_plane0, IJ_plane1)
#define EIDX(pb,rw,x)  (((pb)*HR + (rw))*TX + (x))
#define NELT_E (2*HR*TX)
#define SMEM_BYTES (NELT*8 + NELT_E*4)

// Cross-block reduction state; last block resets it so graph replays are clean.
__device__ float    g_sum    = 0.0f;
__device__ unsigned g_ticket = 0u;

__global__ __launch_bounds__(NT, 4)
void lncc_kernel(const float* __restrict__ pred,
                 const float* __restrict__ targ,
                 float* __restrict__ out)
{
    extern __shared__ char shm[];
    uint2*   const shA  = (uint2*)shm;               // (I,J | I2,J2) packed halves
    __half2* const shEP = (__half2*)(shA + NELT);    // (IJ plane0, IJ plane1)
    __shared__ float blockAcc;

    const int tid = threadIdx.x;
    const int bx = blockIdx.x, by = blockIdx.y;
    const int batch = blockIdx.z / 3;
    const int z0    = (blockIdx.z % 3) * ZCH;

    if (tid == 0) blockAcc = 0.0f;

    // ---- Stage B mapping: ALL 128 threads = 16 rows x 8 x-chunks of 4 ----
    const int  r    = tid >> 3;                 // 0..15
    const int  xq   = tid & 7;
    const int  gy   = by * TY + r - 2;
    const bool rowok = (unsigned)gy < (unsigned)DSZ;
    const int  gx0  = bx * TX + 4 * xq - 2;
    const bool c0 = rowok && ((unsigned)(gx0    ) <= 190u);
    const bool c1 = rowok && ((unsigned)(gx0 + 2) <= 190u);
    const bool c2 = rowok && ((unsigned)(gx0 + 4) <= 190u);
    const bool c3 = rowok && ((unsigned)(gx0 + 6) <= 190u);

    const int gyc = gy < 0 ? 0 : (gy > DSZ - 1 ? DSZ - 1 : gy);
    const long off = (long)batch * DSZ * PL + (long)gyc * DSZ + gx0;
    const float* pB = pred + off;
    const float* tB = targ + off;

    // ---- Stage D mapping: each thread owns 3 adjacent y outputs ----
    const int dy = (tid >> 5) * 3;              // 0,3,6,9
    const int dx = tid & 31;

    float2 Lp[2][4], Lt[2][4];       // prefetched inputs for a plane pair
    const float2 Z2 = make_float2(0.f, 0.f);

#define LOADP(PLN, ZI) do {                                               \
        const int  zi_  = (ZI);                                           \
        const bool zok_ = (unsigned)zi_ < (unsigned)DSZ;                  \
        const long po_  = (long)(zok_ ? zi_ : 0) * PL;                    \
        Lp[PLN][0] = (zok_ && c0) ? *(const float2*)(pB + po_    ) : Z2;  \
        Lp[PLN][1] = (zok_ && c1) ? *(const float2*)(pB + po_ + 2) : Z2;  \
        Lp[PLN][2] = (zok_ && c2) ? *(const float2*)(pB + po_ + 4) : Z2;  \
        Lp[PLN][3] = (zok_ && c3) ? *(const float2*)(pB + po_ + 6) : Z2;  \
        Lt[PLN][0] = (zok_ && c0) ? *(const float2*)(tB + po_    ) : Z2;  \
        Lt[PLN][1] = (zok_ && c1) ? *(const float2*)(tB + po_ + 2) : Z2;  \
        Lt[PLN][2] = (zok_ && c2) ? *(const float2*)(tB + po_ + 4) : Z2;  \
        Lt[PLN][3] = (zok_ && c3) ? *(const float2*)(tB + po_ + 6) : Z2;  \
    } while (0)

    // Computes one plane's x-window sums; stores A/Q channels; leaves IJ in OIJ.
#define BST(PLN, PB, OIJ) do {                                                     \
        const float p0=Lp[PLN][0].x,p1=Lp[PLN][0].y,p2=Lp[PLN][1].x,p3=Lp[PLN][1].y; \
        const float p4=Lp[PLN][2].x,p5=Lp[PLN][2].y,p6=Lp[PLN][3].x,p7=Lp[PLN][3].y; \
        const float q0=Lt[PLN][0].x,q1=Lt[PLN][0].y,q2=Lt[PLN][1].x,q3=Lt[PLN][1].y; \
        const float q4=Lt[PLN][2].x,q5=Lt[PLN][2].y,q6=Lt[PLN][3].x,q7=Lt[PLN][3].y; \
        float4 oI, oJ, oII, oJJ;                                                   \
        oI.x = p0 + p1 + p2 + p3 + p4;                                             \
        oI.y = oI.x - p0 + p5;  oI.z = oI.y - p1 + p6;  oI.w = oI.z - p2 + p7;     \
        oJ.x = q0 + q1 + q2 + q3 + q4;                                             \
        oJ.y = oJ.x - q0 + q5;  oJ.z = oJ.y - q1 + q6;  oJ.w = oJ.z - q2 + q7;     \
        oII.x = fmaf(p4,p4, fmaf(p3,p3, fmaf(p2,p2, fmaf(p1,p1, p0*p0))));         \
        oII.y = fmaf(p5,p5, fmaf(-p0,p0, oII.x));                                  \
        oII.z = fmaf(p6,p6, fmaf(-p1,p1, oII.y));                                  \
        oII.w = fmaf(p7,p7, fmaf(-p2,p2, oII.z));                                  \
        oJJ.x = fmaf(q4,q4, fmaf(q3,q3, fmaf(q2,q2, fmaf(q1,q1, q0*q0))));         \
        oJJ.y = fmaf(q5,q5, fmaf(-q0,q0, oJJ.x));                                  \
        oJJ.z = fmaf(q6,q6, fmaf(-q1,q1, oJJ.y));                                  \
        oJJ.w = fmaf(q7,q7, fmaf(-q2,q2, oJJ.z));                                  \
        (OIJ).x = fmaf(p4,q4, fmaf(p3,q3, fmaf(p2,q2, fmaf(p1,q1, p0*q0))));       \
        (OIJ).y = fmaf(p5,q5, fmaf(-p0,q0, (OIJ).x));                              \
        (OIJ).z = fmaf(p6,q6, fmaf(-p1,q1, (OIJ).y));                              \
        (OIJ).w = fmaf(p7,q7, fmaf(-p2,q2, (OIJ).z));                              \
        const int slot_ = (PB)*2 + (PLN);                                          \
        __half2 t_;                                                               \
        uint4 u0, u1;                                                              \
        t_ = __floats2half2_rn(oI.x,  oJ.x ); u0.x = *(unsigned*)&t_;              \
        t_ = __floats2half2_rn(oII.x, oJJ.x); u0.y = *(unsigned*)&t_;              \
        t_ = __floats2half2_rn(oI.y,  oJ.y ); u0.z = *(unsigned*)&t_;              \
        t_ = __floats2half2_rn(oII.y, oJJ.y); u0.w = *(unsigned*)&t_;              \
        t_ = __floats2half2_rn(oI.z,  oJ.z ); u1.x = *(unsigned*)&t_;              \
        t_ = __floats2half2_rn(oII.z, oJJ.z); u1.y = *(unsigned*)&t_;              \
        t_ = __floats2half2_rn(oI.w,  oJ.w ); u1.z = *(unsigned*)&t_;              \
        t_ = __floats2half2_rn(oII.w, oJJ.w); u1.w = *(unsigned*)&t_;              \
        *(uint4*)&shA[IDX(slot_, r, 4*xq)    ] = u0;                               \
        *(uint4*)&shA[IDX(slot_, r, 4*xq) + 2] = u1;                               \
    } while (0)

    // Pair-packed E store: half2(IJ_plane0, IJ_plane1) per x-output
#define ESTORE(PB, OIJ0, OIJ1) do {                                               \
        __half2 t_; uint4 uE;                                                     \
        t_ = __floats2half2_rn((OIJ0).x, (OIJ1).x); uE.x = *(unsigned*)&t_;       \
        t_ = __floats2half2_rn((OIJ0).y, (OIJ1).y); uE.y = *(unsigned*)&t_;       \
        t_ = __floats2half2_rn((OIJ0).z, (OIJ1).z); uE.z = *(unsigned*)&t_;       \
        t_ = __floats2half2_rn((OIJ0).w, (OIJ1).w); uE.w = *(unsigned*)&t_;       \
        *(uint4*)&shEP[EIDX(PB, r, 4*xq)] = uE;                                   \
    } while (0)

    // z rings: half2 y-sums for (I,J) and (I2,J2), fp32 for IJ — 3 y-outputs
    __half2 ringA[3][5], ringQ[3][5];
    float   ringE[3][5];
    const __half2 HZ = __floats2half2_rn(0.f, 0.f);
#pragma unroll
    for (int o = 0; o < 3; ++o)
#pragma unroll
        for (int s = 0; s < 5; ++s) { ringA[o][s] = HZ; ringQ[o][s] = HZ; ringE[o][s] = 0.f; }
    float acc = 0.f;

    // One plane's D work; E values e0..e6 passed as floats (extracted from shared ep loads)
#define DPLANE(SL, SLOT, IT, E0,E1,E2,E3,E4,E5,E6) do {                           \
        __half2 a0,a1,a2,a3,a4,a5,a6, q0_,q1_,q2_,q3_,q4_,q5_,q6_;                \
        {                                                                         \
            uint2 w;                                                              \
            w = shA[IDX(SL, dy+0, dx)]; a0=*(__half2*)&w.x; q0_=*(__half2*)&w.y;  \
            w = shA[IDX(SL, dy+1, dx)]; a1=*(__half2*)&w.x; q1_=*(__half2*)&w.y;  \
            w = shA[IDX(SL, dy+2, dx)]; a2=*(__half2*)&w.x; q2_=*(__half2*)&w.y;  \
            w = shA[IDX(SL, dy+3, dx)]; a3=*(__half2*)&w.x; q3_=*(__half2*)&w.y;  \
            w = shA[IDX(SL, dy+4, dx)]; a4=*(__half2*)&w.x; q4_=*(__half2*)&w.y;  \
            w = shA[IDX(SL, dy+5, dx)]; a5=*(__half2*)&w.x; q5_=*(__half2*)&w.y;  \
            w = shA[IDX(SL, dy+6, dx)]; a6=*(__half2*)&w.x; q6_=*(__half2*)&w.y;  \
        }                                                                         \
        const __half2 yA0 = __hadd2(__hadd2(__hadd2(a0,a1), __hadd2(a2,a3)), a4); \
        const __half2 yA1 = __hadd2(__hsub2(yA0, a0), a5);                        \
        const __half2 yA2 = __hadd2(__hsub2(yA1, a1), a6);                        \
        const __half2 yQ0 = __hadd2(__hadd2(__hadd2(q0_,q1_), __hadd2(q2_,q3_)), q4_); \
        const __half2 yQ1 = __hadd2(__hsub2(yQ0, q0_), q5_);                      \
        const __half2 yQ2 = __hadd2(__hsub2(yQ1, q1_), q6_);                      \
        const float   yE0 = (((E0) + (E1)) + ((E2) + (E3))) + (E4);               \
        const float   yE1 = yE0 - (E0) + (E5);                                    \
        const float   yE2 = yE1 - (E1) + (E6);                                    \
        ringA[0][SLOT] = yA0;  ringA[1][SLOT] = yA1;  ringA[2][SLOT] = yA2;       \
        ringQ[0][SLOT] = yQ0;  ringQ[1][SLOT] = yQ1;  ringQ[2][SLOT] = yQ2;       \
        ringE[0][SLOT] = yE0;  ringE[1][SLOT] = yE1;  ringE[2][SLOT] = yE2;       \
        if ((IT) >= 4 && (IT) < ZCH + 4) {                                        \
            _Pragma("unroll")                                                     \
            for (int o = 0; o < 3; ++o) {                                         \
                const __half2 SA = __hadd2(__hadd2(__hadd2(ringA[o][0], ringA[o][1]), \
                                   __hadd2(ringA[o][2], ringA[o][3])), ringA[o][4]); \
                const __half2 SQ = __hadd2(__hadd2(__hadd2(ringQ[o][0], ringQ[o][1]), \
                                   __hadd2(ringQ[o][2], ringQ[o][3])), ringQ[o][4]); \
                const float SE = ((ringE[o][0] + ringE[o][1]) +                   \
                                  (ringE[o][2] + ringE[o][3])) + ringE[o][4];     \
                const float2 sa = __half22float2(SA);   /* (SI, SJ)   */          \
                const float2 sq = __half22float2(SQ);   /* (SII, SJJ) */          \
                const float C  = fmaf(125.0f, SE,   -sa.x * sa.y);                \
                const float Vi = fmaf(125.0f, sq.x, -sa.x * sa.x);                \
                const float Vj = fmaf(125.0f, sq.y, -sa.y * sa.y);                \
                acc += __fdividef(C * C, fmaf(Vi, Vj, 2441.40625f));              \
            }                                                                     \
        }                                                                         \
    } while (0)

    // Joint D for the pair: E loaded once, low halves -> plane0, high -> plane1
#define DSTPAIR(PB, SLOT0, SLOT1, IT0) do {                                       \
        const __half2 ep0 = shEP[EIDX(PB, dy+0, dx)];                             \
        const __half2 ep1 = shEP[EIDX(PB, dy+1, dx)];                             \
        const __half2 ep2 = shEP[EIDX(PB, dy+2, dx)];                             \
        const __half2 ep3 = shEP[EIDX(PB, dy+3, dx)];                             \
        const __half2 ep4 = shEP[EIDX(PB, dy+4, dx)];                             \
        const __half2 ep5 = shEP[EIDX(PB, dy+5, dx)];                             \
        const __half2 ep6 = shEP[EIDX(PB, dy+6, dx)];                             \
        DPLANE((PB)*2 + 0, SLOT0, (IT0),                                          \
               __half2float(__low2half(ep0)),  __half2float(__low2half(ep1)),     \
               __half2float(__low2half(ep2)),  __half2float(__low2half(ep3)),     \
               __half2float(__low2half(ep4)),  __half2float(__low2half(ep5)),     \
               __half2float(__low2half(ep6)));                                    \
        DPLANE((PB)*2 + 1, SLOT1, (IT0) + 1,                                      \
               __half2float(__high2half(ep0)), __half2float(__high2half(ep1)),    \
               __half2float(__high2half(ep2)), __half2float(__high2half(ep3)),    \
               __half2float(__high2half(ep4)), __half2float(__high2half(ep5)),    \
               __half2float(__high2half(ep6)));                                   \
    } while (0)

    // preload pair 0 (planes z0-2, z0-1)
    LOADP(0, z0 - 2); LOADP(1, z0 - 1);

    for (int g = 0; g < PAIRS / 5; ++g) {          // 7 groups of 5 pairs
#pragma unroll
        for (int j = 0; j < 5; ++j) {
            const int pi = g * 5 + j;              // pair index 0..34
            const int pb = (g + j) & 1;
            const int it0 = 2 * pi;                // first plane index of pair

            float4 oIJ0, oIJ1;
            BST(0, pb, oIJ0);
            BST(1, pb, oIJ1);
            ESTORE(pb, oIJ0, oIJ1);
            if (pi < PAIRS - 1) {                  // prefetch next pair
                LOADP(0, z0 + 2 * pi);
                LOADP(1, z0 + 2 * pi + 1);
            }
            __syncthreads();

            DSTPAIR(pb, (2 * j) % 5, (2 * j + 1) % 5, it0);
        }
    }

#undef LOADP
#undef BST
#undef ESTORE
#undef DPLANE
#undef DSTPAIR

    // ---- In-block reduction ----
#pragma unroll
    for (int o = 16; o > 0; o >>= 1)
        acc += __shfl_xor_sync(0xffffffffu, acc, o);
    if ((tid & 31) == 0)
        atomicAdd(&blockAcc, acc);
    __syncthreads();

    // ---- Cross-block reduction: last block finalizes and resets state ----
    if (tid == 0) {
        atomicAdd(&g_sum, blockAcc);
        __threadfence();                                   // publish before ticket
        const unsigned t = atomicAdd(&g_ticket, 1u);
        if (t == NBLOCKS - 1) {                            // I'm the last block
            const float s = atomicExch(&g_sum, 0.0f);      // read + reset
            const float INVN = 1.0f / (float)((long)NB * DSZ * DSZ * DSZ);
            out[0] = -s * INVN;
            __threadfence();
            g_ticket = 0u;                                 // restore initial state
        }
    }
}

extern "C" void kernel_launch(void* const* d_in, const int* in_sizes, int n_in,
                              void* d_out, int out_size)
{
    const float* pred = (const float*)d_in[0];
    const float* targ = (const float*)d_in[1];
    float* out = (float*)d_out;

    cudaFuncSetAttribute(lncc_kernel,
                         cudaFuncAttributeMaxDynamicSharedMemorySize, SMEM_BYTES);

    dim3 grid(DSZ / TX, DSZ / TY, NB * 3);   // 6 x 16 x 6 = 576 blocks
    lncc_kernel<<<grid, NT, SMEM_BYTES>>>(pred, targ, out);
}

// round 14
// speedup vs baseline: 3.0977x; 1.0846x over previous
#include <cuda_runtime.h>
#include <cuda_fp16.h>

#define DSZ 192
#define PL  (DSZ * DSZ)
#define NB  2
#define TX  32                   // tile width (x)
#define TY  12                   // tile height (y)
#define ZCH 64                   // z outputs per block (3 chunks cover 192)
#define NT  128
#define HR  16                   // TY + 4  -> 16 rows x 8 chunks = 128 threads exactly
#define PAIRS 35                 // 70 planes processed (68 needed + 2 pad, gated)
#define NBLOCKS (6 * 16 * 6)     // grid size = 576

// A-array: [slot(4 = 2 pairbufs x 2 planes)][row][x] of uint2 {half2(I,J), half2(I2,J2)}
#define IDX(slot,rw,x) (((slot)*HR + (rw))*TX + (x))
#define NELT (4*HR*TX)
// E-array: [pairbuf(2)][row][x] of half2 (IJ_plane0, IJ_plane1)
#define EIDX(pb,rw,x)  (((pb)*HR + (rw))*TX + (x))
#define NELT_E (2*HR*TX)
#define SMEM_BYTES (NELT*8 + NELT_E*4)

// Cross-block reduction state; last block resets it so graph replays are clean.
__device__ float    g_sum    = 0.0f;
__device__ unsigned g_ticket = 0u;

__global__ __launch_bounds__(NT, 4)
void lncc_kernel(const float* __restrict__ pred,
                 const float* __restrict__ targ,
                 float* __restrict__ out)
{
    extern __shared__ char shm[];
    uint2*   const shA  = (uint2*)shm;               // (I,J | I2,J2) packed halves
    __half2* const shEP = (__half2*)(shA + NELT);    // (IJ plane0, IJ plane1)
    __shared__ float blockAcc;

    const int tid = threadIdx.x;
    const int bx = blockIdx.x, by = blockIdx.y;
    const int batch = blockIdx.z / 3;
    const int z0    = (blockIdx.z % 3) * ZCH;

    if (tid == 0) blockAcc = 0.0f;

    // ---- Stage B mapping: ALL 128 threads = 16 rows x 8 x-chunks of 4 ----
    const int  r    = tid >> 3;                 // 0..15
    const int  xq   = tid & 7;
    const int  gy   = by * TY + r - 2;
    const bool rowok = (unsigned)gy < (unsigned)DSZ;
    const int  gx0  = bx * TX + 4 * xq - 2;
    const bool c0 = rowok && ((unsigned)(gx0    ) <= 190u);
    const bool c1 = rowok && ((unsigned)(gx0 + 2) <= 190u);
    const bool c2 = rowok && ((unsigned)(gx0 + 4) <= 190u);
    const bool c3 = rowok && ((unsigned)(gx0 + 6) <= 190u);

    const int gyc = gy < 0 ? 0 : (gy > DSZ - 1 ? DSZ - 1 : gy);
    const long off = (long)batch * DSZ * PL + (long)gyc * DSZ + gx0;
    const float* pB = pred + off;
    const float* tB = targ + off;

    // ---- Stage D mapping: each thread owns 3 adjacent y outputs ----
    const int dy = (tid >> 5) * 3;              // 0,3,6,9
    const int dx = tid & 31;

    float2 Lp[2][4], Lt[2][4];       // prefetched inputs for a plane pair
    const float2 Z2 = make_float2(0.f, 0.f);

#define LOADP(PLN, ZI) do {                                               \
        const int  zi_  = (ZI);                                           \
        const bool zok_ = (unsigned)zi_ < (unsigned)DSZ;                  \
        const long po_  = (long)(zok_ ? zi_ : 0) * PL;                    \
        Lp[PLN][0] = (zok_ && c0) ? *(const float2*)(pB + po_    ) : Z2;  \
        Lp[PLN][1] = (zok_ && c1) ? *(const float2*)(pB + po_ + 2) : Z2;  \
        Lp[PLN][2] = (zok_ && c2) ? *(const float2*)(pB + po_ + 4) : Z2;  \
        Lp[PLN][3] = (zok_ && c3) ? *(const float2*)(pB + po_ + 6) : Z2;  \
        Lt[PLN][0] = (zok_ && c0) ? *(const float2*)(tB + po_    ) : Z2;  \
        Lt[PLN][1] = (zok_ && c1) ? *(const float2*)(tB + po_ + 2) : Z2;  \
        Lt[PLN][2] = (zok_ && c2) ? *(const float2*)(tB + po_ + 4) : Z2;  \
        Lt[PLN][3] = (zok_ && c3) ? *(const float2*)(tB + po_ + 6) : Z2;  \
    } while (0)

    // fp16-SIMD x-window sums: half2(p,q) processes I&J (and II&JJ) together.
    // IJ (cross product) stays fp32 in OIJ.
#define BST(PLN, PB, OIJ) do {                                                     \
        const float p0=Lp[PLN][0].x,p1=Lp[PLN][0].y,p2=Lp[PLN][1].x,p3=Lp[PLN][1].y; \
        const float p4=Lp[PLN][2].x,p5=Lp[PLN][2].y,p6=Lp[PLN][3].x,p7=Lp[PLN][3].y; \
        const float q0=Lt[PLN][0].x,q1=Lt[PLN][0].y,q2=Lt[PLN][1].x,q3=Lt[PLN][1].y; \
        const float q4=Lt[PLN][2].x,q5=Lt[PLN][2].y,q6=Lt[PLN][3].x,q7=Lt[PLN][3].y; \
        const __half2 P0 = __floats2half2_rn(p0,q0), P1 = __floats2half2_rn(p1,q1); \
        const __half2 P2 = __floats2half2_rn(p2,q2), P3 = __floats2half2_rn(p3,q3); \
        const __half2 P4 = __floats2half2_rn(p4,q4), P5 = __floats2half2_rn(p5,q5); \
        const __half2 P6 = __floats2half2_rn(p6,q6), P7 = __floats2half2_rn(p7,q7); \
        const __half2 A0 = __hadd2(__hadd2(__hadd2(P0,P1), __hadd2(P2,P3)), P4);   \
        const __half2 A1 = __hadd2(A0, __hsub2(P5,P0));                            \
        const __half2 A2 = __hadd2(A1, __hsub2(P6,P1));                            \
        const __half2 A3 = __hadd2(A2, __hsub2(P7,P2));                            \
        const __half2 Q0 = __hfma2(P4,P4, __hfma2(P3,P3, __hfma2(P2,P2,           \
                           __hfma2(P1,P1, __hmul2(P0,P0)))));                      \
        const __half2 N0 = __hneg2(P0), N1h = __hneg2(P1), N2h = __hneg2(P2);      \
        const __half2 Q1 = __hfma2(P5,P5, __hfma2(N0, P0, Q0));                    \
        const __half2 Q2 = __hfma2(P6,P6, __hfma2(N1h,P1, Q1));                    \
        const __half2 Q3 = __hfma2(P7,P7, __hfma2(N2h,P2, Q2));                    \
        (OIJ).x = fmaf(p4,q4, fmaf(p3,q3, fmaf(p2,q2, fmaf(p1,q1, p0*q0))));       \
        (OIJ).y = fmaf(p5,q5, fmaf(-p0,q0, (OIJ).x));                              \
        (OIJ).z = fmaf(p6,q6, fmaf(-p1,q1, (OIJ).y));                              \
        (OIJ).w = fmaf(p7,q7, fmaf(-p2,q2, (OIJ).z));                              \
        const int slot_ = (PB)*2 + (PLN);                                          \
        uint4 u0, u1;                                                              \
        u0.x = *(const unsigned*)&A0;  u0.y = *(const unsigned*)&Q0;               \
        u0.z = *(const unsigned*)&A1;  u0.w = *(const unsigned*)&Q1;               \
        u1.x = *(const unsigned*)&A2;  u1.y = *(const unsigned*)&Q2;               \
        u1.z = *(const unsigned*)&A3;  u1.w = *(const unsigned*)&Q3;               \
        *(uint4*)&shA[IDX(slot_, r, 4*xq)    ] = u0;                               \
        *(uint4*)&shA[IDX(slot_, r, 4*xq) + 2] = u1;                               \
    } while (0)

    // Pair-packed E store: half2(IJ_plane0, IJ_plane1) per x-output
#define ESTORE(PB, OIJ0, OIJ1) do {                                               \
        __half2 t_; uint4 uE;                                                     \
        t_ = __floats2half2_rn((OIJ0).x, (OIJ1).x); uE.x = *(unsigned*)&t_;       \
        t_ = __floats2half2_rn((OIJ0).y, (OIJ1).y); uE.y = *(unsigned*)&t_;       \
        t_ = __floats2half2_rn((OIJ0).z, (OIJ1).z); uE.z = *(unsigned*)&t_;       \
        t_ = __floats2half2_rn((OIJ0).w, (OIJ1).w); uE.w = *(unsigned*)&t_;       \
        *(uint4*)&shEP[EIDX(PB, r, 4*xq)] = uE;                                   \
    } while (0)

    // z rings + incremental running z-window sums (refreshed every 5 pairs)
    __half2 ringA[3][5], ringQ[3][5];
    float   ringE[3][5];
    __half2 SzA[3], SzQ[3];
    float   SzE[3];
    const __half2 HZ = __floats2half2_rn(0.f, 0.f);
#pragma unroll
    for (int o = 0; o < 3; ++o) {
        SzA[o] = HZ; SzQ[o] = HZ; SzE[o] = 0.f;
#pragma unroll
        for (int s = 0; s < 5; ++s) { ringA[o][s] = HZ; ringQ[o][s] = HZ; ringE[o][s] = 0.f; }
    }
    float acc = 0.f;

    // One plane's D work: A/Q loads + SIMD y-sums, incremental z update, NCC.
#define DPLANE(SL, SLOT, IT, YE0, YE1, YE2) do {                                  \
        __half2 a0,a1,a2,a3,a4,a5,a6, q0_,q1_,q2_,q3_,q4_,q5_,q6_;                \
        {                                                                         \
            uint2 w;                                                              \
            w = shA[IDX(SL, dy+0, dx)]; a0=*(__half2*)&w.x; q0_=*(__half2*)&w.y;  \
            w = shA[IDX(SL, dy+1, dx)]; a1=*(__half2*)&w.x; q1_=*(__half2*)&w.y;  \
            w = shA[IDX(SL, dy+2, dx)]; a2=*(__half2*)&w.x; q2_=*(__half2*)&w.y;  \
            w = shA[IDX(SL, dy+3, dx)]; a3=*(__half2*)&w.x; q3_=*(__half2*)&w.y;  \
            w = shA[IDX(SL, dy+4, dx)]; a4=*(__half2*)&w.x; q4_=*(__half2*)&w.y;  \
            w = shA[IDX(SL, dy+5, dx)]; a5=*(__half2*)&w.x; q5_=*(__half2*)&w.y;  \
            w = shA[IDX(SL, dy+6, dx)]; a6=*(__half2*)&w.x; q6_=*(__half2*)&w.y;  \
        }                                                                         \
        __half2 ya_[3], yq_[3];                                                   \
        ya_[0] = __hadd2(__hadd2(__hadd2(a0,a1), __hadd2(a2,a3)), a4);            \
        ya_[1] = __hadd2(ya_[0], __hsub2(a5,a0));                                 \
        ya_[2] = __hadd2(ya_[1], __hsub2(a6,a1));                                 \
        yq_[0] = __hadd2(__hadd2(__hadd2(q0_,q1_), __hadd2(q2_,q3_)), q4_);       \
        yq_[1] = __hadd2(yq_[0], __hsub2(q5_,q0_));                               \
        yq_[2] = __hadd2(yq_[1], __hsub2(q6_,q1_));                               \
        const float ye_[3] = { (YE0), (YE1), (YE2) };                             \
        _Pragma("unroll")                                                         \
        for (int o = 0; o < 3; ++o) {                                             \
            SzA[o] = __hadd2(SzA[o], __hsub2(ya_[o], ringA[o][SLOT]));            \
            ringA[o][SLOT] = ya_[o];                                              \
            SzQ[o] = __hadd2(SzQ[o], __hsub2(yq_[o], ringQ[o][SLOT]));            \
            ringQ[o][SLOT] = yq_[o];                                              \
            SzE[o] += ye_[o] - ringE[o][SLOT];                                    \
            ringE[o][SLOT] = ye_[o];                                              \
        }                                                                         \
        if ((IT) >= 4 && (IT) < ZCH + 4) {                                        \
            _Pragma("unroll")                                                     \
            for (int o = 0; o < 3; ++o) {                                         \
                const float2 sa = __half22float2(SzA[o]);   /* (SI, SJ)   */      \
                const float2 sq = __half22float2(SzQ[o]);   /* (SII, SJJ) */      \
                const float C  = fmaf(125.0f, SzE[o], -sa.x * sa.y);              \
                const float Vi = fmaf(125.0f, sq.x,   -sa.x * sa.x);              \
                const float Vj = fmaf(125.0f, sq.y,   -sa.y * sa.y);              \
                acc += __fdividef(C * C, fmaf(Vi, Vj, 2441.40625f));              \
            }                                                                     \
        }                                                                         \
    } while (0)

    // Joint D for the pair: E loaded once (SIMD y-sums over both planes)
#define DSTPAIR(PB, SLOT0, SLOT1, IT0) do {                                       \
        const __half2 ep0 = shEP[EIDX(PB, dy+0, dx)];                             \
        const __half2 ep1 = shEP[EIDX(PB, dy+1, dx)];                             \
        const __half2 ep2 = shEP[EIDX(PB, dy+2, dx)];                             \
        const __half2 ep3 = shEP[EIDX(PB, dy+3, dx)];                             \
        const __half2 ep4 = shEP[EIDX(PB, dy+4, dx)];                             \
        const __half2 ep5 = shEP[EIDX(PB, dy+5, dx)];                             \
        const __half2 ep6 = shEP[EIDX(PB, dy+6, dx)];                             \
        const __half2 yEP0 = __hadd2(__hadd2(__hadd2(ep0,ep1), __hadd2(ep2,ep3)), ep4); \
        const __half2 yEP1 = __hadd2(yEP0, __hsub2(ep5,ep0));                     \
        const __half2 yEP2 = __hadd2(yEP1, __hsub2(ep6,ep1));                     \
        const float2 f0 = __half22float2(yEP0);                                   \
        const float2 f1 = __half22float2(yEP1);                                   \
        const float2 f2 = __half22float2(yEP2);                                   \
        DPLANE((PB)*2 + 0, SLOT0, (IT0),     f0.x, f1.x, f2.x);                   \
        DPLANE((PB)*2 + 1, SLOT1, (IT0) + 1, f0.y, f1.y, f2.y);                   \
    } while (0)

    // preload pair 0 (planes z0-2, z0-1)
    LOADP(0, z0 - 2); LOADP(1, z0 - 1);

    for (int g = 0; g < PAIRS / 5; ++g) {          // 7 groups of 5 pairs
#pragma unroll
        for (int j = 0; j < 5; ++j) {
            const int pi = g * 5 + j;              // pair index 0..34
            const int pb = (g + j) & 1;
            const int it0 = 2 * pi;                // first plane index of pair

            float4 oIJ0, oIJ1;
            BST(0, pb, oIJ0);
            BST(1, pb, oIJ1);
            ESTORE(pb, oIJ0, oIJ1);
            if (pi < PAIRS - 1) {                  // prefetch next pair
                LOADP(0, z0 + 2 * pi);
                LOADP(1, z0 + 2 * pi + 1);
            }
            __syncthreads();

            DSTPAIR(pb, (2 * j) % 5, (2 * j + 1) % 5, it0);
        }
        // Drift control: rebuild running z-sums exactly from the ring
        // (ring always holds the current 5-plane window, any slot order).
#pragma unroll
        for (int o = 0; o < 3; ++o) {
            SzA[o] = __hadd2(__hadd2(__hadd2(ringA[o][0], ringA[o][1]),
                                     __hadd2(ringA[o][2], ringA[o][3])), ringA[o][4]);
            SzQ[o] = __hadd2(__hadd2(__hadd2(ringQ[o][0], ringQ[o][1]),
                                     __hadd2(ringQ[o][2], ringQ[o][3])), ringQ[o][4]);
            SzE[o] = ((ringE[o][0] + ringE[o][1]) +
                      (ringE[o][2] + ringE[o][3])) + ringE[o][4];
        }
    }

#undef LOADP
#undef BST
#undef ESTORE
#undef DPLANE
#undef DSTPAIR

    // ---- In-block reduction ----
#pragma unroll
    for (int o = 16; o > 0; o >>= 1)
        acc += __shfl_xor_sync(0xffffffffu, acc, o);
    if ((tid & 31) == 0)
        atomicAdd(&blockAcc, acc);
    __syncthreads();

    // ---- Cross-block reduction: last block finalizes and resets state ----
    if (tid == 0) {
        atomicAdd(&g_sum, blockAcc);
        __threadfence();                                   // publish before ticket
        const unsigned t = atomicAdd(&g_ticket, 1u);
        if (t == NBLOCKS - 1) {                            // I'm the last block
            const float s = atomicExch(&g_sum, 0.0f);      // read + reset
            const float INVN = 1.0f / (float)((long)NB * DSZ * DSZ * DSZ);
            out[0] = -s * INVN;
            __threadfence();
            g_ticket = 0u;                                 // restore initial state
        }
    }
}

extern "C" void kernel_launch(void* const* d_in, const int* in_sizes, int n_in,
                              void* d_out, int out_size)
{
    const float* pred = (const float*)d_in[0];
    const float* targ = (const float*)d_in[1];
    float* out = (float*)d_out;

    cudaFuncSetAttribute(lncc_kernel,
                         cudaFuncAttributeMaxDynamicSharedMemorySize, SMEM_BYTES);

    dim3 grid(DSZ / TX, DSZ / TY, NB * 3);   // 6 x 16 x 6 = 576 blocks
    lncc_kernel<<<grid, NT, SMEM_BYTES>>>(pred, targ, out);
}